// round 6
// baseline (speedup 1.0000x reference)
#include <cuda_runtime.h>
#include <cuda_bf16.h>
#include <math_constants.h>

// ---------------------------------------------------------------------------
// Dip statistic of a projected sample. Self-contained (no CUB).
//   1. proj = X @ p                  (matvec, warp per row)
//   2. bitonic sort of padded 2^18   (presort + 7 merge stages, in-place)
//   3. Hartigan dip on sorted        (single block; serial hull builds with
//                                     fp32 fast-path pop test; fp32 outer-loop
//                                     scans, no fp64 in hot paths)
// Output: dip/(2N) as float32 scalar.
// All loops in the dip kernel are iteration-capped.
// ---------------------------------------------------------------------------

#define MAXN (1 << 18)   // 262144 >= N = 200000

__device__ float  g_proj[MAXN];       // projection, sorted in place
__device__ int    g_mn[MAXN + 2];
__device__ int    g_mj[MAXN + 2];
__device__ int    g_gcm[MAXN + 2];
__device__ int    g_lcm[MAXN + 2];
__device__ int    g_stkA_i[MAXN + 2];
__device__ float  g_stkA_x[MAXN + 2];
__device__ int    g_stkB_i[MAXN + 2];
__device__ float  g_stkB_x[MAXN + 2];

// 1-based access to the sorted array (in-bounds for i in [1, MAXN])
#define XF(i) g_proj[(i) - 1]

// ---------------------------------------------------------------------------
// Matvec: one warp per row, D = 128 (32 lanes x float4)
// ---------------------------------------------------------------------------
__global__ void matvec_kernel(const float* __restrict__ X,
                              const float* __restrict__ PV,
                              const int*   __restrict__ idx,
                              int N, int D)
{
    int gtid = blockIdx.x * blockDim.x + threadIdx.x;
    int warp = gtid >> 5;
    int lane = gtid & 31;
    if (warp >= N) return;

    const float* p = PV + (size_t)(*idx) * D;
    const float4* row = reinterpret_cast<const float4*>(X + (size_t)warp * D);
    const float4* p4  = reinterpret_cast<const float4*>(p);

    float4 a = row[lane];
    float4 b = p4[lane];
    float s = fmaf(a.x, b.x, fmaf(a.y, b.y, fmaf(a.z, b.z, a.w * b.w)));

    #pragma unroll
    for (int o = 16; o > 0; o >>= 1)
        s += __shfl_xor_sync(0xFFFFFFFFu, s, o);

    if (lane == 0) g_proj[warp] = s;
}

__global__ void pad_kernel(int N)
{
    int i = N + blockIdx.x * blockDim.x + threadIdx.x;
    if (i < MAXN) g_proj[i] = CUDART_INF_F;
}

// ---------------------------------------------------------------------------
// Bitonic sort, in place over g_proj[0..MAXN).
// ---------------------------------------------------------------------------
__device__ __forceinline__ void cmpxchg(float& a, float& b, bool up)
{
    if (up ? (a > b) : (a < b)) { float t = a; a = b; b = t; }
}

__global__ void bitonic_presort_kernel()
{
    __shared__ float sh[2048];
    int base = blockIdx.x * 2048;
    int t = threadIdx.x;                 // 1024 threads
    sh[t]        = g_proj[base + t];
    sh[t + 1024] = g_proj[base + t + 1024];
    __syncthreads();

    bool asc = ((base & 2048) == 0);
    for (int size = 2; size <= 2048; size <<= 1) {
        for (int s = size >> 1; s > 0; s >>= 1) {
            int i = ((t & ~(s - 1)) << 1) | (t & (s - 1));
            int j = i | s;
            bool up = (((i & size) == 0) == asc);
            float a = sh[i], b = sh[j];
            cmpxchg(a, b, up);
            sh[i] = a; sh[j] = b;
            __syncthreads();
        }
    }
    g_proj[base + t]        = sh[t];
    g_proj[base + t + 1024] = sh[t + 1024];
}

__global__ void bitonic_global_kernel(int size, int s)
{
    int t = blockIdx.x * blockDim.x + threadIdx.x;   // MAXN/2 threads
    int i = ((t & ~(s - 1)) << 1) | (t & (s - 1));
    int j = i | s;
    bool up = ((i & size) == 0);
    float a = g_proj[i], b = g_proj[j];
    cmpxchg(a, b, up);
    g_proj[i] = a; g_proj[j] = b;
}

__global__ void bitonic_merge_shared_kernel(int size)
{
    __shared__ float sh[2048];
    int base = blockIdx.x * 2048;
    int t = threadIdx.x;
    sh[t]        = g_proj[base + t];
    sh[t + 1024] = g_proj[base + t + 1024];
    __syncthreads();

    bool up = ((base & size) == 0);
    for (int s = 1024; s > 0; s >>= 1) {
        int i = ((t & ~(s - 1)) << 1) | (t & (s - 1));
        int j = i | s;
        float a = sh[i], b = sh[j];
        cmpxchg(a, b, up);
        sh[i] = a; sh[j] = b;
        __syncthreads();
    }
    g_proj[base + t]        = sh[t];
    g_proj[base + t + 1024] = sh[t + 1024];
}

// ---------------------------------------------------------------------------
// Pop test: pop iff (xa-xm)*(m-mm) >= (xm-xmm)*(a-m)   [reference semantics]
// fp32 fast path with conservative margin; exact fp64 fallback.
// ---------------------------------------------------------------------------
__device__ __forceinline__ bool pop_test(int a, float xa, int m, float xm,
                                         int mm, float xmm)
{
    float f1 = (xa - xm) * (float)(m - mm);
    float f2 = (xm - xmm) * (float)(a - m);
    float diff = f1 - f2;
    float margin = 1e-5f * (fabsf(f1) + fabsf(f2)) + 1e-30f;
    if (diff >  margin) return true;
    if (diff < -margin) return false;
    double p1 = ((double)xa - (double)xm) * (double)(m - mm);
    double p2 = ((double)xm - (double)xmm) * (double)(a - m);
    return p1 >= p2;
}

// ---------------------------------------------------------------------------
// Dip kernel: single block of 1024 threads.
//   Phase 1: tid 0 builds mn[], tid 512 builds mj[] (register stacks).
//   Phase 2: tid 0 / tid 32 walk chains in parallel; tid 0 runs the fp32
//            d-loop; all threads do fp32 segment scans (segment-outer,
//            block-stride inner); shuffle max reduce.
// ---------------------------------------------------------------------------
__global__ void dip_kernel(int N, float* __restrict__ out)
{
    const int tid = threadIdx.x;

    __shared__ int s_brk;
    __shared__ int s_ig, s_lgcm, s_ih, s_llcm;
    __shared__ float s_warp[32];
    __shared__ float s_max;

    if (N < 4 || XF(1) == XF(N)) {
        if (tid == 0) out[0] = (float)(1.0 / (2.0 * (double)max(N, 1)));
        return;
    }

    // --- Phase 1: hull pointer builds ------------------------------------
    if (tid == 0) {
        int d = 0;
        int   top_i = 1;  float top_x = XF(1);
        int   bel_i = 0;  float bel_x = 0.0f;
        g_stkA_i[0] = 1; g_stkA_x[0] = top_x;
        float xn = XF(2);
        for (int j = 2; j <= N; j++) {
            float xj = xn; xn = XF(j + 1);      // prefetch (XF(N+1) = inf pad)
            int guard = d + 1;
            while (d >= 1 && guard-- > 0) {
                if (!pop_test(j, xj, top_i, top_x, bel_i, bel_x)) break;
                d--;
                top_i = bel_i; top_x = bel_x;
                if (d >= 1) { bel_i = g_stkA_i[d - 1]; bel_x = g_stkA_x[d - 1]; }
            }
            g_mn[j] = top_i;
            d++;
            g_stkA_i[d] = j; g_stkA_x[d] = xj;
            bel_i = top_i; bel_x = top_x;
            top_i = j;     top_x = xj;
        }
    } else if (tid == 512) {
        int d = 0;
        int   top_i = N;  float top_x = XF(N);
        int   bel_i = 0;  float bel_x = 0.0f;
        g_stkB_i[0] = N; g_stkB_x[0] = top_x;
        float xn = XF(N - 1);
        for (int k = N - 1; k >= 1; k--) {
            float xk = xn; xn = XF((k > 1) ? (k - 1) : 1);   // in-bounds prefetch
            int guard = d + 1;
            while (d >= 1 && guard-- > 0) {
                if (!pop_test(k, xk, top_i, top_x, bel_i, bel_x)) break;
                d--;
                top_i = bel_i; top_x = bel_x;
                if (d >= 1) { bel_i = g_stkB_i[d - 1]; bel_x = g_stkB_x[d - 1]; }
            }
            g_mj[k] = top_i;
            d++;
            g_stkB_i[d] = k; g_stkB_x[d] = xk;
            bel_i = top_i; bel_x = top_x;
            top_i = k;     top_x = xk;
        }
    }
    __syncthreads();

    // --- Phase 2: outer loop (iteration-capped) ---------------------------
    int low = 1, high = N;             // thread 0 state
    double dip = 1.0;
    int ig0 = 0, ih0 = 0;
    __shared__ int s_low, s_high;
    if (tid == 0) { s_low = low; s_high = high; }

    for (int iter = 0; iter < 3000; iter++) {
        __syncthreads();   // separates prior bottom s_brk read from rewrites

        // parallel chain walks (two different warps)
        if (tid == 0) {
            g_gcm[1] = s_high;
            int i = 1;
            while (g_gcm[i] > s_low && i <= N) { g_gcm[i + 1] = g_mn[g_gcm[i]]; i++; }
            s_lgcm = i;
        } else if (tid == 32) {
            g_lcm[1] = s_low;
            int i = 1;
            while (g_lcm[i] < s_high && i <= N) { g_lcm[i + 1] = g_mj[g_lcm[i]]; i++; }
            s_llcm = i;
        }
        __syncthreads();

        if (tid == 0) {
            int l_gcm = s_lgcm, l_lcm = s_llcm;
            int ig = l_gcm, ix = l_gcm - 1;
            int ih = l_lcm, iv = 2;

            float d = 0.0f;
            if (l_gcm != 2 || l_lcm != 2) {
                int cap = 3 * N + 10;
                do {
                    int gcmix = g_gcm[ix];
                    int lcmiv = g_lcm[iv];
                    if (gcmix > lcmiv) {
                        int gcmi1 = g_gcm[ix + 1];
                        float t = ((float)(lcmiv - gcmi1) + 1.0f)
                                - (XF(lcmiv) - XF(gcmi1)) * (float)(gcmix - gcmi1)
                                  / (XF(gcmix) - XF(gcmi1));
                        iv++;
                        if (t >= d) { d = t; ig = ix + 1; ih = iv - 1; }
                    } else {
                        int lcmiv1 = g_lcm[iv - 1];
                        float t = (XF(gcmix) - XF(lcmiv1)) * (float)(lcmiv - lcmiv1)
                                  / (XF(lcmiv) - XF(lcmiv1))
                                - ((float)(gcmix - lcmiv1) - 1.0f);
                        ix--;
                        if (t > d) { d = t; ig = ix + 1; ih = iv; }
                    }
                    if (ix < 1) ix = 1;
                    if (iv > l_lcm) iv = l_lcm;
                } while (g_gcm[ix] != g_lcm[iv] && --cap > 0);
            } else {
                d = 1.0f;
            }

            if ((double)d < dip) {
                s_brk = 1;
            } else {
                s_brk = 0;
                s_ig = ig; s_ih = ih;
                ig0 = ig; ih0 = ih;
            }
        }
        __syncthreads();
        if (s_brk) break;

        // ---- fp32 segment max scans, segment-outer / block-stride inner --
        float lm = 1.0f;

        if (tid < 512) {
            // gcm side: segments j in [s_ig, s_lgcm), seg = [gcm[j+1], gcm[j]]
            for (int j = s_ig; j < s_lgcm; j++) {
                int jb = g_gcm[j + 1];
                int je = g_gcm[j];
                if (je - jb > 1) {
                    float xb = XF(jb), xe = XF(je);
                    if (xe != xb) {
                        float C = (float)(je - jb) / (xe - xb);
                        for (int pos = jb + tid; pos <= je; pos += 512) {
                            float t = (float)(pos - jb + 1) - (XF(pos) - xb) * C;
                            lm = fmaxf(lm, t);
                        }
                    }
                }
            }
        } else {
            int t2 = tid - 512;
            // lcm side: segments j in [s_ih, s_llcm), seg = [lcm[j], lcm[j+1]]
            for (int j = s_ih; j < s_llcm; j++) {
                int jb = g_lcm[j];
                int je = g_lcm[j + 1];
                if (je - jb > 1) {
                    float xb = XF(jb), xe = XF(je);
                    if (xe != xb) {
                        float C = (float)(je - jb) / (xe - xb);
                        for (int pos = jb + t2; pos <= je; pos += 512) {
                            float t = (XF(pos) - xb) * C - ((float)(pos - jb) - 1.0f);
                            lm = fmaxf(lm, t);
                        }
                    }
                }
            }
        }

        // ---- shuffle max reduce ----
        #pragma unroll
        for (int o = 16; o > 0; o >>= 1)
            lm = fmaxf(lm, __shfl_xor_sync(0xFFFFFFFFu, lm, o));
        if ((tid & 31) == 0) s_warp[tid >> 5] = lm;
        __syncthreads();
        if (tid < 32) {
            float v = s_warp[tid];
            #pragma unroll
            for (int o = 16; o > 0; o >>= 1)
                v = fmaxf(v, __shfl_xor_sync(0xFFFFFFFFu, v, o));
            if (tid == 0) s_max = v;
        }
        __syncthreads();

        if (tid == 0) {
            double dip_new = (double)s_max;
            if (dip < dip_new) dip = dip_new;
            int nlow = g_gcm[ig0], nhigh = g_lcm[ih0];
            if (low == nlow && high == nhigh) {
                s_brk = 1;
            } else {
                s_brk = 0;
                low = nlow; high = nhigh;
                s_low = low; s_high = high;
            }
        }
        __syncthreads();
        if (s_brk) break;
    }

    if (tid == 0) out[0] = (float)(dip / (2.0 * (double)N));
}

// ---------------------------------------------------------------------------
// Launch: pure kernel launches, no runtime API calls.
// ---------------------------------------------------------------------------
extern "C" void kernel_launch(void* const* d_in, const int* in_sizes, int n_in,
                              void* d_out, int out_size)
{
    const float* X   = (const float*)d_in[0];
    const float* PV  = (const float*)d_in[1];
    const int*   idx = (const int*)d_in[2];
    float*       out = (float*)d_out;

    const int D = 128;
    const int N = in_sizes[0] / D;

    // 1. projection + pad
    matvec_kernel<<<(N + 7) / 8, 256>>>(X, PV, idx, N, D);
    pad_kernel<<<(MAXN - N + 255) / 256, 256>>>(N);

    // 2. bitonic sort (in place on g_proj)
    bitonic_presort_kernel<<<MAXN / 2048, 1024>>>();
    for (int size = 4096; size <= MAXN; size <<= 1) {
        for (int s = size >> 1; s >= 2048; s >>= 1)
            bitonic_global_kernel<<<(MAXN / 2) / 256, 256>>>(size, s);
        bitonic_merge_shared_kernel<<<MAXN / 2048, 1024>>>(size);
    }

    // 3. dip
    dip_kernel<<<1, 1024>>>(N, out);
}

// round 7
// speedup vs baseline: 19.7640x; 19.7640x over previous
#include <cuda_runtime.h>
#include <cuda_bf16.h>
#include <math_constants.h>

// ---------------------------------------------------------------------------
// Dip statistic of a projected sample. Self-contained (no CUB).
//   1. proj = X @ p                  (matvec, warp per row)
//   2. bitonic sort of padded 2^18   (in-place)
//   3. parallel hull-pointer build   (chunked monotone stack, 3 phases)
//   4. Hartigan dip outer loop       (single block, fp32 scans)
// Output: dip/(2N) as float32 scalar.
// ---------------------------------------------------------------------------

#define MAXN  (1 << 18)   // 262144 >= N = 200000
#define KCH   256         // chunks per side
#define CSMAX 1024        // max chunk size (MAXN / KCH)

__device__ float g_proj[MAXN];        // projection, sorted in place
__device__ int   g_mn[MAXN + 2];
__device__ int   g_mj[MAXN + 2];
__device__ int   g_gcm[MAXN + 2];
__device__ int   g_lcm[MAXN + 2];
// phase-1 scratch
__device__ int   g_lcl_i[2 * KCH * CSMAX];
__device__ float g_lcl_x[2 * KCH * CSMAX];
__device__ int   g_nsurv[2 * KCH];
__device__ int   g_arena_i[2 * (MAXN + 2)];
__device__ float g_arena_x[2 * (MAXN + 2)];
__device__ int   g_arena_prev[2 * (MAXN + 2)];
__device__ int   g_snap_head[2 * KCH];

// 1-based access to the sorted array (in-bounds for i in [1, MAXN])
#define XF(i) g_proj[(i) - 1]

// ---------------------------------------------------------------------------
// Matvec: one warp per row, D = 128 (32 lanes x float4)
// ---------------------------------------------------------------------------
__global__ void matvec_kernel(const float* __restrict__ X,
                              const float* __restrict__ PV,
                              const int*   __restrict__ idx,
                              int N, int D)
{
    int gtid = blockIdx.x * blockDim.x + threadIdx.x;
    int warp = gtid >> 5;
    int lane = gtid & 31;
    if (warp >= N) return;

    const float* p = PV + (size_t)(*idx) * D;
    const float4* row = reinterpret_cast<const float4*>(X + (size_t)warp * D);
    const float4* p4  = reinterpret_cast<const float4*>(p);

    float4 a = row[lane];
    float4 b = p4[lane];
    float s = fmaf(a.x, b.x, fmaf(a.y, b.y, fmaf(a.z, b.z, a.w * b.w)));

    #pragma unroll
    for (int o = 16; o > 0; o >>= 1)
        s += __shfl_xor_sync(0xFFFFFFFFu, s, o);

    if (lane == 0) g_proj[warp] = s;
}

__global__ void pad_kernel(int N)
{
    int i = N + blockIdx.x * blockDim.x + threadIdx.x;
    if (i < MAXN) g_proj[i] = CUDART_INF_F;
}

// ---------------------------------------------------------------------------
// Bitonic sort, in place over g_proj[0..MAXN).
// ---------------------------------------------------------------------------
__device__ __forceinline__ void cmpxchg(float& a, float& b, bool up)
{
    if (up ? (a > b) : (a < b)) { float t = a; a = b; b = t; }
}

__global__ void bitonic_presort_kernel()
{
    __shared__ float sh[2048];
    int base = blockIdx.x * 2048;
    int t = threadIdx.x;                 // 1024 threads
    sh[t]        = g_proj[base + t];
    sh[t + 1024] = g_proj[base + t + 1024];
    __syncthreads();

    bool asc = ((base & 2048) == 0);
    for (int size = 2; size <= 2048; size <<= 1) {
        for (int s = size >> 1; s > 0; s >>= 1) {
            int i = ((t & ~(s - 1)) << 1) | (t & (s - 1));
            int j = i | s;
            bool up = (((i & size) == 0) == asc);
            float a = sh[i], b = sh[j];
            cmpxchg(a, b, up);
            sh[i] = a; sh[j] = b;
            __syncthreads();
        }
    }
    g_proj[base + t]        = sh[t];
    g_proj[base + t + 1024] = sh[t + 1024];
}

__global__ void bitonic_global_kernel(int size, int s)
{
    int t = blockIdx.x * blockDim.x + threadIdx.x;   // MAXN/2 threads
    int i = ((t & ~(s - 1)) << 1) | (t & (s - 1));
    int j = i | s;
    bool up = ((i & size) == 0);
    float a = g_proj[i], b = g_proj[j];
    cmpxchg(a, b, up);
    g_proj[i] = a; g_proj[j] = b;
}

__global__ void bitonic_merge_shared_kernel(int size)
{
    __shared__ float sh[2048];
    int base = blockIdx.x * 2048;
    int t = threadIdx.x;
    sh[t]        = g_proj[base + t];
    sh[t + 1024] = g_proj[base + t + 1024];
    __syncthreads();

    bool up = ((base & size) == 0);
    for (int s = 1024; s > 0; s >>= 1) {
        int i = ((t & ~(s - 1)) << 1) | (t & (s - 1));
        int j = i | s;
        float a = sh[i], b = sh[j];
        cmpxchg(a, b, up);
        sh[i] = a; sh[j] = b;
        __syncthreads();
    }
    g_proj[base + t]        = sh[t];
    g_proj[base + t + 1024] = sh[t + 1024];
}

// ---------------------------------------------------------------------------
// Pop test: pop iff (xa-xm)*(m-mm) >= (xm-xmm)*(a-m)   [reference semantics]
// fp32 fast path with conservative margin; exact fp64 fallback (identical
// rounding to the reference's float64 evaluation).
// ---------------------------------------------------------------------------
__device__ __forceinline__ bool pop_test(int a, float xa, int m, float xm,
                                         int mm, float xmm)
{
    float f1 = (xa - xm) * (float)(m - mm);
    float f2 = (xm - xmm) * (float)(a - m);
    float diff = f1 - f2;
    float margin = 1e-5f * (fabsf(f1) + fabsf(f2)) + 1e-30f;
    if (diff >  margin) return true;
    if (diff < -margin) return false;
    double p1 = ((double)xa - (double)xm) * (double)(m - mm);
    double p2 = ((double)xm - (double)xmm) * (double)(a - m);
    return p1 >= p2;
}

// ---------------------------------------------------------------------------
// Phase A: per-chunk local monotone stack; survivors stay in g_lcl arrays.
// Threads [0,KCH) = mn side (left->right), [KCH,2*KCH) = mj side.
// ---------------------------------------------------------------------------
__global__ void hullA_kernel(int N, int cs)
{
    int gid = blockIdx.x * blockDim.x + threadIdx.x;
    if (gid >= 2 * KCH) return;
    int side = gid >> 8;          // KCH == 256
    int c    = gid & (KCH - 1);

    int n_el;
    if (side == 0) { int s0 = 1 + c * cs; n_el = min(cs, N - s0 + 1); }
    else           { int s0 = N - c * cs; n_el = min(cs, s0); }
    if (n_el <= 0) { g_nsurv[gid] = 0; return; }

    int*   sti = g_lcl_i + gid * CSMAX;
    float* stx = g_lcl_x + gid * CSMAX;
    int d = 0;
    int top_i = 0, bel_i = 0; float top_x = 0.0f, bel_x = 0.0f;

    for (int p = 0; p < n_el; p++) {
        int j = (side == 0) ? (1 + c * cs + p) : (N - c * cs - p);
        float xj = XF(j);
        int guard = d;
        while (d >= 2 && guard-- >= 0) {
            if (!pop_test(j, xj, top_i, top_x, bel_i, bel_x)) break;
            d--;
            top_i = bel_i; top_x = bel_x;
            if (d >= 2) { bel_i = sti[d - 2]; bel_x = stx[d - 2]; }
        }
        sti[d] = j; stx[d] = xj; d++;
        bel_i = top_i; bel_x = top_x;
        top_i = j;     top_x = xj;
    }
    g_nsurv[gid] = d;
}

// ---------------------------------------------------------------------------
// Phase B: sequential merge of survivors into append-only arena stacks.
// Thread 0 = mn side, thread 32 = mj side. Snapshots = head pointers.
// ---------------------------------------------------------------------------
__global__ void merge_kernel(int N)
{
    int tid = threadIdx.x;
    int side;
    if (tid == 0) side = 0; else if (tid == 32) side = 1; else return;

    int off = side * (MAXN + 2);
    int h = -1, anext = off, d = 0;
    int top_i = 0, bel_i = 0; float top_x = 0.0f, bel_x = 0.0f;
    long budget = 4L * N + 1000;

    for (int k = 0; k < KCH; k++) {
        g_snap_head[side * KCH + k] = h;
        int gid = side * KCH + k;
        int ns = g_nsurv[gid];
        const int*   si = g_lcl_i + gid * CSMAX;
        const float* sx = g_lcl_x + gid * CSMAX;
        for (int q = 0; q < ns; q++) {
            int j = si[q]; float xj = sx[q];
            while (d >= 2 && budget-- > 0) {
                if (!pop_test(j, xj, top_i, top_x, bel_i, bel_x)) break;
                h = g_arena_prev[h];
                d--;
                top_i = bel_i; top_x = bel_x;
                if (d >= 2) {
                    int pb = g_arena_prev[h];
                    bel_i = g_arena_i[pb]; bel_x = g_arena_x[pb];
                }
            }
            g_arena_i[anext] = j; g_arena_x[anext] = xj; g_arena_prev[anext] = h;
            h = anext++; d++;
            bel_i = top_i; bel_x = top_x;
            top_i = j;     top_x = xj;
        }
    }
}

// ---------------------------------------------------------------------------
// Phase C: replay each chunk seeded with its true incoming stack (arena
// linked list below, local array above); writes exact mn[] / mj[].
// ---------------------------------------------------------------------------
__global__ void hullC_kernel(int N, int cs)
{
    int gid = blockIdx.x * blockDim.x + threadIdx.x;
    if (gid >= 2 * KCH) return;
    int side = gid >> 8;
    int c    = gid & (KCH - 1);

    int n_el;
    if (side == 0) { int s0 = 1 + c * cs; n_el = min(cs, N - s0 + 1); }
    else           { int s0 = N - c * cs; n_el = min(cs, s0); }
    if (n_el <= 0) return;

    int*   sti = g_lcl_i + gid * CSMAX;   // reuse as phase-C local stack
    float* stx = g_lcl_x + gid * CSMAX;
    int lcl_d = 0;
    int ah = g_snap_head[side * KCH + c];
    int sentinel = (side == 0) ? 1 : N;

    int top_i = 0, bel_i = 0; float top_x = 0.0f, bel_x = 0.0f;
    bool have_top = false;
    if (ah >= 0) {
        top_i = g_arena_i[ah]; top_x = g_arena_x[ah]; have_top = true;
        int pb = g_arena_prev[ah];
        if (pb >= 0) { bel_i = g_arena_i[pb]; bel_x = g_arena_x[pb]; }
    }

    long guard = (long)N + CSMAX + 100;
    for (int p = 0; p < n_el; p++) {
        int j = (side == 0) ? (1 + c * cs + p) : (N - c * cs - p);
        float xj = XF(j);
        while (have_top && top_i != sentinel && guard-- > 0) {
            if (!pop_test(j, xj, top_i, top_x, bel_i, bel_x)) break;
            // pop one level
            if (lcl_d > 0) lcl_d--;
            else            ah = g_arena_prev[ah];
            top_i = bel_i; top_x = bel_x;
            // refill bel = level-2 of combined stack
            if (lcl_d >= 2)      { bel_i = sti[lcl_d - 2]; bel_x = stx[lcl_d - 2]; }
            else if (lcl_d == 1) { if (ah >= 0) { bel_i = g_arena_i[ah]; bel_x = g_arena_x[ah]; } }
            else if (ah >= 0) {
                int pb = g_arena_prev[ah];
                if (pb >= 0) { bel_i = g_arena_i[pb]; bel_x = g_arena_x[pb]; }
            }
        }
        int mnval = have_top ? top_i : j;
        if (side == 0) g_mn[j] = mnval; else g_mj[j] = mnval;
        sti[lcl_d] = j; stx[lcl_d] = xj; lcl_d++;
        bel_i = top_i; bel_x = top_x;
        top_i = j;     top_x = xj;
        have_top = true;
    }
}

// ---------------------------------------------------------------------------
// Dip kernel: single block of 1024 threads — phase 2 only (outer loop).
// ---------------------------------------------------------------------------
__global__ void dip_kernel(int N, float* __restrict__ out)
{
    const int tid = threadIdx.x;

    __shared__ int s_brk;
    __shared__ int s_ig, s_lgcm, s_ih, s_llcm;
    __shared__ float s_warp[32];
    __shared__ float s_max;

    if (N < 4 || XF(1) == XF(N)) {
        if (tid == 0) out[0] = (float)(1.0 / (2.0 * (double)max(N, 1)));
        return;
    }

    int low = 1, high = N;             // thread 0 state
    double dip = 1.0;
    int ig0 = 0, ih0 = 0;
    __shared__ int s_low, s_high;
    if (tid == 0) { s_low = low; s_high = high; }

    for (int iter = 0; iter < 3000; iter++) {
        __syncthreads();   // separates prior bottom s_brk read from rewrites

        // parallel chain walks (two different warps)
        if (tid == 0) {
            g_gcm[1] = s_high;
            int i = 1;
            while (g_gcm[i] > s_low && i <= N) { g_gcm[i + 1] = g_mn[g_gcm[i]]; i++; }
            s_lgcm = i;
        } else if (tid == 32) {
            g_lcm[1] = s_low;
            int i = 1;
            while (g_lcm[i] < s_high && i <= N) { g_lcm[i + 1] = g_mj[g_lcm[i]]; i++; }
            s_llcm = i;
        }
        __syncthreads();

        if (tid == 0) {
            int l_gcm = s_lgcm, l_lcm = s_llcm;
            int ig = l_gcm, ix = l_gcm - 1;
            int ih = l_lcm, iv = 2;

            float d = 0.0f;
            if (l_gcm != 2 || l_lcm != 2) {
                int cap = 3 * N + 10;
                do {
                    int gcmix = g_gcm[ix];
                    int lcmiv = g_lcm[iv];
                    if (gcmix > lcmiv) {
                        int gcmi1 = g_gcm[ix + 1];
                        float t = ((float)(lcmiv - gcmi1) + 1.0f)
                                - (XF(lcmiv) - XF(gcmi1)) * (float)(gcmix - gcmi1)
                                  / (XF(gcmix) - XF(gcmi1));
                        iv++;
                        if (t >= d) { d = t; ig = ix + 1; ih = iv - 1; }
                    } else {
                        int lcmiv1 = g_lcm[iv - 1];
                        float t = (XF(gcmix) - XF(lcmiv1)) * (float)(lcmiv - lcmiv1)
                                  / (XF(lcmiv) - XF(lcmiv1))
                                - ((float)(gcmix - lcmiv1) - 1.0f);
                        ix--;
                        if (t > d) { d = t; ig = ix + 1; ih = iv; }
                    }
                    if (ix < 1) ix = 1;
                    if (iv > l_lcm) iv = l_lcm;
                } while (g_gcm[ix] != g_lcm[iv] && --cap > 0);
            } else {
                d = 1.0f;
            }

            if ((double)d < dip) {
                s_brk = 1;
            } else {
                s_brk = 0;
                s_ig = ig; s_ih = ih;
                ig0 = ig; ih0 = ih;
            }
        }
        __syncthreads();
        if (s_brk) break;

        // ---- fp32 segment max scans, segment-outer / block-stride inner --
        float lm = 1.0f;

        if (tid < 512) {
            for (int j = s_ig; j < s_lgcm; j++) {
                int jb = g_gcm[j + 1];
                int je = g_gcm[j];
                if (je - jb > 1) {
                    float xb = XF(jb), xe = XF(je);
                    if (xe != xb) {
                        float C = (float)(je - jb) / (xe - xb);
                        for (int pos = jb + tid; pos <= je; pos += 512) {
                            float t = (float)(pos - jb + 1) - (XF(pos) - xb) * C;
                            lm = fmaxf(lm, t);
                        }
                    }
                }
            }
        } else {
            int t2 = tid - 512;
            for (int j = s_ih; j < s_llcm; j++) {
                int jb = g_lcm[j];
                int je = g_lcm[j + 1];
                if (je - jb > 1) {
                    float xb = XF(jb), xe = XF(je);
                    if (xe != xb) {
                        float C = (float)(je - jb) / (xe - xb);
                        for (int pos = jb + t2; pos <= je; pos += 512) {
                            float t = (XF(pos) - xb) * C - ((float)(pos - jb) - 1.0f);
                            lm = fmaxf(lm, t);
                        }
                    }
                }
            }
        }

        // ---- shuffle max reduce ----
        #pragma unroll
        for (int o = 16; o > 0; o >>= 1)
            lm = fmaxf(lm, __shfl_xor_sync(0xFFFFFFFFu, lm, o));
        if ((tid & 31) == 0) s_warp[tid >> 5] = lm;
        __syncthreads();
        if (tid < 32) {
            float v = s_warp[tid];
            #pragma unroll
            for (int o = 16; o > 0; o >>= 1)
                v = fmaxf(v, __shfl_xor_sync(0xFFFFFFFFu, v, o));
            if (tid == 0) s_max = v;
        }
        __syncthreads();

        if (tid == 0) {
            double dip_new = (double)s_max;
            if (dip < dip_new) dip = dip_new;
            int nlow = g_gcm[ig0], nhigh = g_lcm[ih0];
            if (low == nlow && high == nhigh) {
                s_brk = 1;
            } else {
                s_brk = 0;
                low = nlow; high = nhigh;
                s_low = low; s_high = high;
            }
        }
        __syncthreads();
        if (s_brk) break;
    }

    if (tid == 0) out[0] = (float)(dip / (2.0 * (double)N));
}

// ---------------------------------------------------------------------------
// Launch: pure kernel launches, no runtime API calls.
// ---------------------------------------------------------------------------
extern "C" void kernel_launch(void* const* d_in, const int* in_sizes, int n_in,
                              void* d_out, int out_size)
{
    const float* X   = (const float*)d_in[0];
    const float* PV  = (const float*)d_in[1];
    const int*   idx = (const int*)d_in[2];
    float*       out = (float*)d_out;

    const int D = 128;
    const int N = in_sizes[0] / D;
    const int cs = (N + KCH - 1) / KCH;

    // 1. projection + pad
    matvec_kernel<<<(N + 7) / 8, 256>>>(X, PV, idx, N, D);
    pad_kernel<<<(MAXN - N + 255) / 256, 256>>>(N);

    // 2. bitonic sort (in place on g_proj)
    bitonic_presort_kernel<<<MAXN / 2048, 1024>>>();
    for (int size = 4096; size <= MAXN; size <<= 1) {
        for (int s = size >> 1; s >= 2048; s >>= 1)
            bitonic_global_kernel<<<(MAXN / 2) / 256, 256>>>(size, s);
        bitonic_merge_shared_kernel<<<MAXN / 2048, 1024>>>(size);
    }

    // 3. parallel hull-pointer build (mn / mj)
    hullA_kernel<<<8, 64>>>(N, cs);
    merge_kernel<<<1, 64>>>(N);
    hullC_kernel<<<8, 64>>>(N, cs);

    // 4. dip outer loop
    dip_kernel<<<1, 1024>>>(N, out);
}

// round 8
// speedup vs baseline: 20.1548x; 1.0198x over previous
#include <cuda_runtime.h>
#include <cuda_bf16.h>
#include <math_constants.h>

// ---------------------------------------------------------------------------
// Dip statistic of a projected sample. Self-contained (no CUB).
//   1. proj = X @ p                  (matvec, warp per row)
//   2. bitonic sort of padded 2^18   (tile-8192 presort + 15 global steps)
//   3. parallel hull-pointer build   (512 chunks/side, 3 phases)
//   4. Hartigan dip outer loop       (single block, fp32 scans)
// Output: dip/(2N) as float32 scalar.
// ---------------------------------------------------------------------------

#define MAXN  (1 << 18)   // 262144 >= N = 200000
#define KCH   512         // chunks per side
#define CSMAX 512         // max chunk size (MAXN / KCH)
#define TILE  8192        // bitonic shared tile

__device__ float g_proj[MAXN];        // projection, sorted in place
__device__ int   g_mn[MAXN + 2];
__device__ int   g_mj[MAXN + 2];
__device__ int   g_gcm[MAXN + 2];
__device__ int   g_lcm[MAXN + 2];
// hull scratch
__device__ int   g_lcl_i[2 * KCH * CSMAX];
__device__ float g_lcl_x[2 * KCH * CSMAX];
__device__ int   g_nsurv[2 * KCH];
__device__ int   g_arena_i[2 * (MAXN + 2)];
__device__ float g_arena_x[2 * (MAXN + 2)];
__device__ int   g_arena_prev[2 * (MAXN + 2)];
__device__ int   g_snap_head[2 * KCH];

// 1-based access to the sorted array (in-bounds for i in [1, MAXN])
#define XF(i) g_proj[(i) - 1]

// ---------------------------------------------------------------------------
// Matvec: one warp per row, D = 128 (32 lanes x float4)
// ---------------------------------------------------------------------------
__global__ void matvec_kernel(const float* __restrict__ X,
                              const float* __restrict__ PV,
                              const int*   __restrict__ idx,
                              int N, int D)
{
    int gtid = blockIdx.x * blockDim.x + threadIdx.x;
    int warp = gtid >> 5;
    int lane = gtid & 31;
    if (warp >= N) return;

    const float* p = PV + (size_t)(*idx) * D;
    const float4* row = reinterpret_cast<const float4*>(X + (size_t)warp * D);
    const float4* p4  = reinterpret_cast<const float4*>(p);

    float4 a = row[lane];
    float4 b = p4[lane];
    float s = fmaf(a.x, b.x, fmaf(a.y, b.y, fmaf(a.z, b.z, a.w * b.w)));

    #pragma unroll
    for (int o = 16; o > 0; o >>= 1)
        s += __shfl_xor_sync(0xFFFFFFFFu, s, o);

    if (lane == 0) g_proj[warp] = s;
}

__global__ void pad_kernel(int N)
{
    int i = N + blockIdx.x * blockDim.x + threadIdx.x;
    if (i < MAXN) g_proj[i] = CUDART_INF_F;
}

// ---------------------------------------------------------------------------
// Bitonic sort, in place over g_proj[0..MAXN). Tile = 8192 (32 KB smem).
// ---------------------------------------------------------------------------
__device__ __forceinline__ void cmpxchg(float& a, float& b, bool up)
{
    if (up ? (a > b) : (a < b)) { float t = a; a = b; b = t; }
}

// Sort each 8192-element tile; tile direction alternates with bit 13 of base.
__global__ void bitonic_presort_kernel()
{
    __shared__ float sh[TILE];
    int base = blockIdx.x * TILE;
    int t = threadIdx.x;                 // 1024 threads
    #pragma unroll
    for (int v = 0; v < TILE / 1024; v++)
        sh[t + v * 1024] = g_proj[base + t + v * 1024];
    __syncthreads();

    bool asc = ((base & TILE) == 0);
    for (int size = 2; size <= TILE; size <<= 1) {
        for (int s = size >> 1; s > 0; s >>= 1) {
            #pragma unroll
            for (int v = 0; v < TILE / 2048; v++) {
                int idx = t + v * 1024;      // pair index
                int i = ((idx & ~(s - 1)) << 1) | (idx & (s - 1));
                int j = i | s;
                bool up = (((i & size) == 0) == asc);
                float a = sh[i], b = sh[j];
                cmpxchg(a, b, up);
                sh[i] = a; sh[j] = b;
            }
            __syncthreads();
        }
    }
    #pragma unroll
    for (int v = 0; v < TILE / 1024; v++)
        g_proj[base + t + v * 1024] = sh[t + v * 1024];
}

// One global compare-exchange step of merge stage `size`, stride s >= TILE.
__global__ void bitonic_global_kernel(int size, int s)
{
    int t = blockIdx.x * blockDim.x + threadIdx.x;   // MAXN/2 threads
    int i = ((t & ~(s - 1)) << 1) | (t & (s - 1));
    int j = i | s;
    bool up = ((i & size) == 0);
    float a = g_proj[i], b = g_proj[j];
    cmpxchg(a, b, up);
    g_proj[i] = a; g_proj[j] = b;
}

// Finish merge stage `size` (>= 2*TILE): strides TILE/2..1 in shared memory.
__global__ void bitonic_merge_shared_kernel(int size)
{
    __shared__ float sh[TILE];
    int base = blockIdx.x * TILE;
    int t = threadIdx.x;
    #pragma unroll
    for (int v = 0; v < TILE / 1024; v++)
        sh[t + v * 1024] = g_proj[base + t + v * 1024];
    __syncthreads();

    bool up = ((base & size) == 0);
    for (int s = TILE / 2; s > 0; s >>= 1) {
        #pragma unroll
        for (int v = 0; v < TILE / 2048; v++) {
            int idx = t + v * 1024;
            int i = ((idx & ~(s - 1)) << 1) | (idx & (s - 1));
            int j = i | s;
            float a = sh[i], b = sh[j];
            cmpxchg(a, b, up);
            sh[i] = a; sh[j] = b;
        }
        __syncthreads();
    }
    #pragma unroll
    for (int v = 0; v < TILE / 1024; v++)
        g_proj[base + t + v * 1024] = sh[t + v * 1024];
}

// ---------------------------------------------------------------------------
// Pop test: pop iff (xa-xm)*(m-mm) >= (xm-xmm)*(a-m)   [reference semantics]
// fp32 fast path with conservative margin; exact fp64 fallback.
// ---------------------------------------------------------------------------
__device__ __forceinline__ bool pop_test(int a, float xa, int m, float xm,
                                         int mm, float xmm)
{
    float f1 = (xa - xm) * (float)(m - mm);
    float f2 = (xm - xmm) * (float)(a - m);
    float diff = f1 - f2;
    float margin = 1e-5f * (fabsf(f1) + fabsf(f2)) + 1e-30f;
    if (diff >  margin) return true;
    if (diff < -margin) return false;
    double p1 = ((double)xa - (double)xm) * (double)(m - mm);
    double p2 = ((double)xm - (double)xmm) * (double)(a - m);
    return p1 >= p2;
}

// ---------------------------------------------------------------------------
// Phase A: per-chunk local monotone stack; survivors stay in g_lcl arrays.
// gid in [0, KCH) = mn side (left->right), [KCH, 2*KCH) = mj side.
// ---------------------------------------------------------------------------
__global__ void hullA_kernel(int N, int cs)
{
    int gid = blockIdx.x * blockDim.x + threadIdx.x;
    if (gid >= 2 * KCH) return;
    int side = gid / KCH;
    int c    = gid % KCH;

    int n_el;
    if (side == 0) { int s0 = 1 + c * cs; n_el = min(cs, N - s0 + 1); }
    else           { int s0 = N - c * cs; n_el = min(cs, s0); }
    if (n_el <= 0) { g_nsurv[gid] = 0; return; }

    int*   sti = g_lcl_i + gid * CSMAX;
    float* stx = g_lcl_x + gid * CSMAX;
    int d = 0;
    int top_i = 0, bel_i = 0; float top_x = 0.0f, bel_x = 0.0f;

    for (int p = 0; p < n_el; p++) {
        int j = (side == 0) ? (1 + c * cs + p) : (N - c * cs - p);
        float xj = XF(j);
        while (d >= 2) {                 // bounded: each iter does d--
            if (!pop_test(j, xj, top_i, top_x, bel_i, bel_x)) break;
            d--;
            top_i = bel_i; top_x = bel_x;
            if (d >= 2) { bel_i = sti[d - 2]; bel_x = stx[d - 2]; }
        }
        sti[d] = j; stx[d] = xj; d++;
        bel_i = top_i; bel_x = top_x;
        top_i = j;     top_x = xj;
    }
    g_nsurv[gid] = d;
}

// ---------------------------------------------------------------------------
// Phase B: sequential merge of survivors into append-only arena stacks.
// Thread 0 = mn side, thread 32 = mj side. Snapshots = head pointers.
// ---------------------------------------------------------------------------
__global__ void merge_kernel(int N)
{
    int tid = threadIdx.x;
    int side;
    if (tid == 0) side = 0; else if (tid == 32) side = 1; else return;

    int off = side * (MAXN + 2);
    int h = -1, anext = off, d = 0;
    int top_i = 0, bel_i = 0; float top_x = 0.0f, bel_x = 0.0f;
    long budget = 4L * N + 1000;

    for (int k = 0; k < KCH; k++) {
        g_snap_head[side * KCH + k] = h;
        int gid = side * KCH + k;
        int ns = g_nsurv[gid];
        const int*   si = g_lcl_i + gid * CSMAX;
        const float* sx = g_lcl_x + gid * CSMAX;
        for (int q = 0; q < ns; q++) {
            int j = si[q]; float xj = sx[q];
            while (d >= 2 && budget-- > 0) {
                if (!pop_test(j, xj, top_i, top_x, bel_i, bel_x)) break;
                h = g_arena_prev[h];
                d--;
                top_i = bel_i; top_x = bel_x;
                if (d >= 2) {
                    int pb = g_arena_prev[h];
                    bel_i = g_arena_i[pb]; bel_x = g_arena_x[pb];
                }
            }
            g_arena_i[anext] = j; g_arena_x[anext] = xj; g_arena_prev[anext] = h;
            h = anext++; d++;
            bel_i = top_i; bel_x = top_x;
            top_i = j;     top_x = xj;
        }
    }
}

// ---------------------------------------------------------------------------
// Phase C: replay each chunk seeded with its true incoming stack (arena
// linked list below, local array above); writes exact mn[] / mj[].
// ---------------------------------------------------------------------------
__global__ void hullC_kernel(int N, int cs)
{
    int gid = blockIdx.x * blockDim.x + threadIdx.x;
    if (gid >= 2 * KCH) return;
    int side = gid / KCH;
    int c    = gid % KCH;

    int n_el;
    if (side == 0) { int s0 = 1 + c * cs; n_el = min(cs, N - s0 + 1); }
    else           { int s0 = N - c * cs; n_el = min(cs, s0); }
    if (n_el <= 0) return;

    int*   sti = g_lcl_i + gid * CSMAX;   // reuse as phase-C local stack
    float* stx = g_lcl_x + gid * CSMAX;
    int lcl_d = 0;
    int ah = g_snap_head[side * KCH + c];
    int sentinel = (side == 0) ? 1 : N;

    int top_i = 0, bel_i = 0; float top_x = 0.0f, bel_x = 0.0f;
    bool have_top = false;
    if (ah >= 0) {
        top_i = g_arena_i[ah]; top_x = g_arena_x[ah]; have_top = true;
        int pb = g_arena_prev[ah];
        if (pb >= 0) { bel_i = g_arena_i[pb]; bel_x = g_arena_x[pb]; }
    }

    for (int p = 0; p < n_el; p++) {
        int j = (side == 0) ? (1 + c * cs + p) : (N - c * cs - p);
        float xj = XF(j);
        // bounded: each iter pops one level of a finite acyclic stack
        while (have_top && top_i != sentinel) {
            if (!pop_test(j, xj, top_i, top_x, bel_i, bel_x)) break;
            if (lcl_d > 0) lcl_d--;
            else            ah = g_arena_prev[ah];
            top_i = bel_i; top_x = bel_x;
            if (lcl_d >= 2)      { bel_i = sti[lcl_d - 2]; bel_x = stx[lcl_d - 2]; }
            else if (lcl_d == 1) { if (ah >= 0) { bel_i = g_arena_i[ah]; bel_x = g_arena_x[ah]; } }
            else if (ah >= 0) {
                int pb = g_arena_prev[ah];
                if (pb >= 0) { bel_i = g_arena_i[pb]; bel_x = g_arena_x[pb]; }
            }
            if (lcl_d == 0 && ah < 0) have_top = false;
        }
        int mnval = have_top ? top_i : j;
        if (side == 0) g_mn[j] = mnval; else g_mj[j] = mnval;
        sti[lcl_d] = j; stx[lcl_d] = xj; lcl_d++;
        bel_i = top_i; bel_x = top_x;
        top_i = j;     top_x = xj;
        have_top = true;
    }
}

// ---------------------------------------------------------------------------
// Dip kernel: single block of 1024 threads — outer loop.
// ---------------------------------------------------------------------------
__global__ void dip_kernel(int N, float* __restrict__ out)
{
    const int tid = threadIdx.x;

    __shared__ int s_brk;
    __shared__ int s_ig, s_lgcm, s_ih, s_llcm;
    __shared__ float s_warp[32];
    __shared__ float s_max;

    if (N < 4 || XF(1) == XF(N)) {
        if (tid == 0) out[0] = (float)(1.0 / (2.0 * (double)max(N, 1)));
        return;
    }

    int low = 1, high = N;             // thread 0 state
    double dip = 1.0;
    int ig0 = 0, ih0 = 0;
    __shared__ int s_low, s_high;
    if (tid == 0) { s_low = low; s_high = high; }

    for (int iter = 0; iter < 3000; iter++) {
        __syncthreads();   // separates prior bottom s_brk read from rewrites

        // parallel chain walks (two different warps)
        if (tid == 0) {
            g_gcm[1] = s_high;
            int i = 1;
            while (g_gcm[i] > s_low && i <= N) { g_gcm[i + 1] = g_mn[g_gcm[i]]; i++; }
            s_lgcm = i;
        } else if (tid == 32) {
            g_lcm[1] = s_low;
            int i = 1;
            while (g_lcm[i] < s_high && i <= N) { g_lcm[i + 1] = g_mj[g_lcm[i]]; i++; }
            s_llcm = i;
        }
        __syncthreads();

        if (tid == 0) {
            int l_gcm = s_lgcm, l_lcm = s_llcm;
            int ig = l_gcm, ix = l_gcm - 1;
            int ih = l_lcm, iv = 2;

            float d = 0.0f;
            if (l_gcm != 2 || l_lcm != 2) {
                int cap = 3 * N + 10;
                do {
                    int gcmix = g_gcm[ix];
                    int lcmiv = g_lcm[iv];
                    if (gcmix > lcmiv) {
                        int gcmi1 = g_gcm[ix + 1];
                        float t = ((float)(lcmiv - gcmi1) + 1.0f)
                                - (XF(lcmiv) - XF(gcmi1)) * (float)(gcmix - gcmi1)
                                  / (XF(gcmix) - XF(gcmi1));
                        iv++;
                        if (t >= d) { d = t; ig = ix + 1; ih = iv - 1; }
                    } else {
                        int lcmiv1 = g_lcm[iv - 1];
                        float t = (XF(gcmix) - XF(lcmiv1)) * (float)(lcmiv - lcmiv1)
                                  / (XF(lcmiv) - XF(lcmiv1))
                                - ((float)(gcmix - lcmiv1) - 1.0f);
                        ix--;
                        if (t > d) { d = t; ig = ix + 1; ih = iv; }
                    }
                    if (ix < 1) ix = 1;
                    if (iv > l_lcm) iv = l_lcm;
                } while (g_gcm[ix] != g_lcm[iv] && --cap > 0);
            } else {
                d = 1.0f;
            }

            if ((double)d < dip) {
                s_brk = 1;
            } else {
                s_brk = 0;
                s_ig = ig; s_ih = ih;
                ig0 = ig; ih0 = ih;
            }
        }
        __syncthreads();
        if (s_brk) break;

        // ---- fp32 segment max scans, segment-outer / block-stride inner --
        float lm = 1.0f;

        if (tid < 512) {
            for (int j = s_ig; j < s_lgcm; j++) {
                int jb = g_gcm[j + 1];
                int je = g_gcm[j];
                if (je - jb > 1) {
                    float xb = XF(jb), xe = XF(je);
                    if (xe != xb) {
                        float C = (float)(je - jb) / (xe - xb);
                        for (int pos = jb + tid; pos <= je; pos += 512) {
                            float t = (float)(pos - jb + 1) - (XF(pos) - xb) * C;
                            lm = fmaxf(lm, t);
                        }
                    }
                }
            }
        } else {
            int t2 = tid - 512;
            for (int j = s_ih; j < s_llcm; j++) {
                int jb = g_lcm[j];
                int je = g_lcm[j + 1];
                if (je - jb > 1) {
                    float xb = XF(jb), xe = XF(je);
                    if (xe != xb) {
                        float C = (float)(je - jb) / (xe - xb);
                        for (int pos = jb + t2; pos <= je; pos += 512) {
                            float t = (XF(pos) - xb) * C - ((float)(pos - jb) - 1.0f);
                            lm = fmaxf(lm, t);
                        }
                    }
                }
            }
        }

        // ---- shuffle max reduce ----
        #pragma unroll
        for (int o = 16; o > 0; o >>= 1)
            lm = fmaxf(lm, __shfl_xor_sync(0xFFFFFFFFu, lm, o));
        if ((tid & 31) == 0) s_warp[tid >> 5] = lm;
        __syncthreads();
        if (tid < 32) {
            float v = s_warp[tid];
            #pragma unroll
            for (int o = 16; o > 0; o >>= 1)
                v = fmaxf(v, __shfl_xor_sync(0xFFFFFFFFu, v, o));
            if (tid == 0) s_max = v;
        }
        __syncthreads();

        if (tid == 0) {
            double dip_new = (double)s_max;
            if (dip < dip_new) dip = dip_new;
            int nlow = g_gcm[ig0], nhigh = g_lcm[ih0];
            if (low == nlow && high == nhigh) {
                s_brk = 1;
            } else {
                s_brk = 0;
                low = nlow; high = nhigh;
                s_low = low; s_high = high;
            }
        }
        __syncthreads();
        if (s_brk) break;
    }

    if (tid == 0) out[0] = (float)(dip / (2.0 * (double)N));
}

// ---------------------------------------------------------------------------
// Launch: pure kernel launches, no runtime API calls.
// ---------------------------------------------------------------------------
extern "C" void kernel_launch(void* const* d_in, const int* in_sizes, int n_in,
                              void* d_out, int out_size)
{
    const float* X   = (const float*)d_in[0];
    const float* PV  = (const float*)d_in[1];
    const int*   idx = (const int*)d_in[2];
    float*       out = (float*)d_out;

    const int D = 128;
    const int N = in_sizes[0] / D;
    const int cs = (N + KCH - 1) / KCH;

    // 1. projection + pad
    matvec_kernel<<<(N + 7) / 8, 256>>>(X, PV, idx, N, D);
    pad_kernel<<<(MAXN - N + 255) / 256, 256>>>(N);

    // 2. bitonic sort (in place on g_proj), tile = 8192
    bitonic_presort_kernel<<<MAXN / TILE, 1024>>>();
    for (int size = 2 * TILE; size <= MAXN; size <<= 1) {
        for (int s = size >> 1; s >= TILE; s >>= 1)
            bitonic_global_kernel<<<(MAXN / 2) / 256, 256>>>(size, s);
        bitonic_merge_shared_kernel<<<MAXN / TILE, 1024>>>(size);
    }

    // 3. parallel hull-pointer build (mn / mj)
    hullA_kernel<<<(2 * KCH + 63) / 64, 64>>>(N, cs);
    merge_kernel<<<1, 64>>>(N);
    hullC_kernel<<<(2 * KCH + 63) / 64, 64>>>(N, cs);

    // 4. dip outer loop
    dip_kernel<<<1, 1024>>>(N, out);
}

// round 9
// speedup vs baseline: 32.9544x; 1.6351x over previous
#include <cuda_runtime.h>
#include <cuda_bf16.h>
#include <math_constants.h>

// ---------------------------------------------------------------------------
// Dip statistic of a projected sample. Self-contained (no CUB).
//   1. proj = X @ p                  (matvec, warp per row)
//   2. bitonic sort of padded 2^18   (tile-8192 presort + global steps)
//   3. parallel hull-pointer build   (512 chunks/side; A, M1, M2, M3, C)
//   4. Hartigan dip outer loop       (single block, shared-memory chains)
// Output: dip/(2N) as float32 scalar.
// ---------------------------------------------------------------------------

#define MAXN  (1 << 18)   // 262144 >= N = 200000
#define KCH   512         // chunks per side
#define CSMAX 512         // max chunk size (MAXN / KCH)
#define GRP   32          // groups per side
#define CPG   16          // chunks per group (GRP*CPG == KCH)
#define GSMAX (CPG * CSMAX)            // 8192: max survivors per group
#define ARENA_M2 (GRP * GSMAX)         // 262144: M2 region per side
#define ARENA_PS (ARENA_M2 + KCH * CSMAX)  // 524288 per side
#define TILE  8192        // bitonic shared tile
#define CCAP  2048        // shared chain capacity per side (dip kernel)

__device__ float g_proj[MAXN];        // projection, sorted in place
__device__ int   g_mn[MAXN + 2];
__device__ int   g_mj[MAXN + 2];
__device__ int   g_gcm[MAXN + 2];     // dip chain spill (index)
__device__ float g_gcm_x[MAXN + 2];   // dip chain spill (x)
__device__ int   g_lcm[MAXN + 2];
__device__ float g_lcm_x[MAXN + 2];
// hull scratch
__device__ int   g_lcl_i[2 * KCH * CSMAX];
__device__ float g_lcl_x[2 * KCH * CSMAX];
__device__ int   g_nsurv[2 * KCH];
__device__ int   g_grp_i[2 * GRP * GSMAX];
__device__ float g_grp_x[2 * GRP * GSMAX];
__device__ int   g_ngrp[2 * GRP];
__device__ int   g_arena_i[2 * ARENA_PS];
__device__ float g_arena_x[2 * ARENA_PS];
__device__ int   g_arena_prev[2 * ARENA_PS];
__device__ int   g_snapG[2 * GRP];
__device__ int   g_snap_head[2 * KCH];

// 1-based access to the sorted array (in-bounds for i in [1, MAXN])
#define XF(i) g_proj[(i) - 1]

// ---------------------------------------------------------------------------
// Matvec: one warp per row, D = 128 (32 lanes x float4)
// ---------------------------------------------------------------------------
__global__ void matvec_kernel(const float* __restrict__ X,
                              const float* __restrict__ PV,
                              const int*   __restrict__ idx,
                              int N, int D)
{
    int gtid = blockIdx.x * blockDim.x + threadIdx.x;
    int warp = gtid >> 5;
    int lane = gtid & 31;
    if (warp >= N) return;

    const float* p = PV + (size_t)(*idx) * D;
    const float4* row = reinterpret_cast<const float4*>(X + (size_t)warp * D);
    const float4* p4  = reinterpret_cast<const float4*>(p);

    float4 a = row[lane];
    float4 b = p4[lane];
    float s = fmaf(a.x, b.x, fmaf(a.y, b.y, fmaf(a.z, b.z, a.w * b.w)));

    #pragma unroll
    for (int o = 16; o > 0; o >>= 1)
        s += __shfl_xor_sync(0xFFFFFFFFu, s, o);

    if (lane == 0) g_proj[warp] = s;
}

__global__ void pad_kernel(int N)
{
    int i = N + blockIdx.x * blockDim.x + threadIdx.x;
    if (i < MAXN) g_proj[i] = CUDART_INF_F;
}

// ---------------------------------------------------------------------------
// Bitonic sort, in place over g_proj[0..MAXN). Tile = 8192 (32 KB smem).
// ---------------------------------------------------------------------------
__device__ __forceinline__ void cmpxchg(float& a, float& b, bool up)
{
    if (up ? (a > b) : (a < b)) { float t = a; a = b; b = t; }
}

__global__ void bitonic_presort_kernel()
{
    __shared__ float sh[TILE];
    int base = blockIdx.x * TILE;
    int t = threadIdx.x;                 // 1024 threads
    #pragma unroll
    for (int v = 0; v < TILE / 1024; v++)
        sh[t + v * 1024] = g_proj[base + t + v * 1024];
    __syncthreads();

    bool asc = ((base & TILE) == 0);
    for (int size = 2; size <= TILE; size <<= 1) {
        for (int s = size >> 1; s > 0; s >>= 1) {
            #pragma unroll
            for (int v = 0; v < TILE / 2048; v++) {
                int idx = t + v * 1024;      // pair index
                int i = ((idx & ~(s - 1)) << 1) | (idx & (s - 1));
                int j = i | s;
                bool up = (((i & size) == 0) == asc);
                float a = sh[i], b = sh[j];
                cmpxchg(a, b, up);
                sh[i] = a; sh[j] = b;
            }
            __syncthreads();
        }
    }
    #pragma unroll
    for (int v = 0; v < TILE / 1024; v++)
        g_proj[base + t + v * 1024] = sh[t + v * 1024];
}

__global__ void bitonic_global_kernel(int size, int s)
{
    int t = blockIdx.x * blockDim.x + threadIdx.x;   // MAXN/2 threads
    int i = ((t & ~(s - 1)) << 1) | (t & (s - 1));
    int j = i | s;
    bool up = ((i & size) == 0);
    float a = g_proj[i], b = g_proj[j];
    cmpxchg(a, b, up);
    g_proj[i] = a; g_proj[j] = b;
}

__global__ void bitonic_merge_shared_kernel(int size)
{
    __shared__ float sh[TILE];
    int base = blockIdx.x * TILE;
    int t = threadIdx.x;
    #pragma unroll
    for (int v = 0; v < TILE / 1024; v++)
        sh[t + v * 1024] = g_proj[base + t + v * 1024];
    __syncthreads();

    bool up = ((base & size) == 0);
    for (int s = TILE / 2; s > 0; s >>= 1) {
        #pragma unroll
        for (int v = 0; v < TILE / 2048; v++) {
            int idx = t + v * 1024;
            int i = ((idx & ~(s - 1)) << 1) | (idx & (s - 1));
            int j = i | s;
            float a = sh[i], b = sh[j];
            cmpxchg(a, b, up);
            sh[i] = a; sh[j] = b;
        }
        __syncthreads();
    }
    #pragma unroll
    for (int v = 0; v < TILE / 1024; v++)
        g_proj[base + t + v * 1024] = sh[t + v * 1024];
}

// ---------------------------------------------------------------------------
// Pop test: pop iff (xa-xm)*(m-mm) >= (xm-xmm)*(a-m)   [reference semantics]
// fp32 fast path with conservative margin; exact fp64 fallback.
// ---------------------------------------------------------------------------
__device__ __forceinline__ bool pop_test(int a, float xa, int m, float xm,
                                         int mm, float xmm)
{
    float f1 = (xa - xm) * (float)(m - mm);
    float f2 = (xm - xmm) * (float)(a - m);
    float diff = f1 - f2;
    float margin = 1e-5f * (fabsf(f1) + fabsf(f2)) + 1e-30f;
    if (diff >  margin) return true;
    if (diff < -margin) return false;
    double p1 = ((double)xa - (double)xm) * (double)(m - mm);
    double p2 = ((double)xm - (double)xmm) * (double)(a - m);
    return p1 >= p2;
}

// ---------------------------------------------------------------------------
// Phase A: per-chunk local monotone stack; survivors stay in g_lcl arrays.
// ---------------------------------------------------------------------------
__global__ void hullA_kernel(int N, int cs)
{
    int gid = blockIdx.x * blockDim.x + threadIdx.x;
    if (gid >= 2 * KCH) return;
    int side = gid / KCH;
    int c    = gid % KCH;

    int n_el;
    if (side == 0) { int s0 = 1 + c * cs; n_el = min(cs, N - s0 + 1); }
    else           { int s0 = N - c * cs; n_el = min(cs, s0); }
    if (n_el <= 0) { g_nsurv[gid] = 0; return; }

    int*   sti = g_lcl_i + (size_t)gid * CSMAX;
    float* stx = g_lcl_x + (size_t)gid * CSMAX;
    int d = 0;
    int top_i = 0, bel_i = 0; float top_x = 0.0f, bel_x = 0.0f;

    for (int p = 0; p < n_el; p++) {
        int j = (side == 0) ? (1 + c * cs + p) : (N - c * cs - p);
        float xj = XF(j);
        while (d >= 2) {
            if (!pop_test(j, xj, top_i, top_x, bel_i, bel_x)) break;
            d--;
            top_i = bel_i; top_x = bel_x;
            if (d >= 2) { bel_i = sti[d - 2]; bel_x = stx[d - 2]; }
        }
        sti[d] = j; stx[d] = xj; d++;
        bel_i = top_i; bel_x = top_x;
        top_i = j;     top_x = xj;
    }
    g_nsurv[gid] = d;
}

// ---------------------------------------------------------------------------
// M1: fold each group's 16 chunks of survivors into a group survivor list.
// ---------------------------------------------------------------------------
__global__ void mergeM1_kernel()
{
    int gid = blockIdx.x * blockDim.x + threadIdx.x;
    if (gid >= 2 * GRP) return;
    int side = gid / GRP, g = gid % GRP;

    int*   out_i = g_grp_i + (size_t)(side * GRP + g) * GSMAX;
    float* out_x = g_grp_x + (size_t)(side * GRP + g) * GSMAX;
    int d = 0;
    int top_i = 0, bel_i = 0; float top_x = 0.0f, bel_x = 0.0f;

    for (int k = 0; k < CPG; k++) {
        int cid = side * KCH + g * CPG + k;
        int ns = g_nsurv[cid];
        const int*   si = g_lcl_i + (size_t)cid * CSMAX;
        const float* sx = g_lcl_x + (size_t)cid * CSMAX;
        for (int q = 0; q < ns; q++) {
            int j = si[q]; float xj = sx[q];
            while (d >= 2) {
                if (!pop_test(j, xj, top_i, top_x, bel_i, bel_x)) break;
                d--;
                top_i = bel_i; top_x = bel_x;
                if (d >= 2) { bel_i = out_i[d - 2]; bel_x = out_x[d - 2]; }
            }
            out_i[d] = j; out_x[d] = xj; d++;
            bel_i = top_i; bel_x = top_x;
            top_i = j;     top_x = xj;
        }
    }
    g_ngrp[side * GRP + g] = d;
}

// ---------------------------------------------------------------------------
// M2: serial merge of the 32 group lists into the arena; group snapshots.
// Thread 0 = mn side, thread 32 = mj side.
// ---------------------------------------------------------------------------
__global__ void mergeM2_kernel()
{
    int tid = threadIdx.x;
    int side;
    if (tid == 0) side = 0; else if (tid == 32) side = 1; else return;

    int base = side * ARENA_PS;
    int h = -1, anext = base, d = 0;
    int top_i = 0, bel_i = 0; float top_x = 0.0f, bel_x = 0.0f;

    for (int g = 0; g < GRP; g++) {
        g_snapG[side * GRP + g] = h;
        int ng = g_ngrp[side * GRP + g];
        const int*   si = g_grp_i + (size_t)(side * GRP + g) * GSMAX;
        const float* sx = g_grp_x + (size_t)(side * GRP + g) * GSMAX;
        for (int q = 0; q < ng; q++) {
            int j = si[q]; float xj = sx[q];
            while (d >= 2) {
                if (!pop_test(j, xj, top_i, top_x, bel_i, bel_x)) break;
                h = g_arena_prev[h];
                d--;
                top_i = bel_i; top_x = bel_x;
                if (d >= 2) {
                    int pb = g_arena_prev[h];
                    bel_i = g_arena_i[pb]; bel_x = g_arena_x[pb];
                }
            }
            g_arena_i[anext] = j; g_arena_x[anext] = xj; g_arena_prev[anext] = h;
            h = anext++; d++;
            bel_i = top_i; bel_x = top_x;
            top_i = j;     top_x = xj;
        }
    }
}

// ---------------------------------------------------------------------------
// M3: per group, replay the group's chunk-survivor stream from its true
// incoming stack; append to the group's arena slab; per-chunk snapshots.
// ---------------------------------------------------------------------------
__global__ void mergeM3_kernel(int N)
{
    int gid = blockIdx.x * blockDim.x + threadIdx.x;
    if (gid >= 2 * GRP) return;
    int side = gid / GRP, g = gid % GRP;
    int sentinel = (side == 0) ? 1 : N;

    int h = g_snapG[side * GRP + g];
    int anext = side * ARENA_PS + ARENA_M2 + g * GSMAX;

    int top_i = 0, bel_i = 0; float top_x = 0.0f, bel_x = 0.0f;
    bool have_top = false;
    if (h >= 0) {
        top_i = g_arena_i[h]; top_x = g_arena_x[h]; have_top = true;
        int pb = g_arena_prev[h];
        if (pb >= 0) { bel_i = g_arena_i[pb]; bel_x = g_arena_x[pb]; }
    }

    for (int k = 0; k < CPG; k++) {
        int cid = side * KCH + g * CPG + k;
        g_snap_head[cid] = h;
        int ns = g_nsurv[cid];
        const int*   si = g_lcl_i + (size_t)cid * CSMAX;
        const float* sx = g_lcl_x + (size_t)cid * CSMAX;
        for (int q = 0; q < ns; q++) {
            int j = si[q]; float xj = sx[q];
            while (have_top && top_i != sentinel) {
                if (!pop_test(j, xj, top_i, top_x, bel_i, bel_x)) break;
                h = g_arena_prev[h];
                if (h >= 0) {
                    top_i = g_arena_i[h]; top_x = g_arena_x[h];
                    int pb = g_arena_prev[h];
                    if (pb >= 0) { bel_i = g_arena_i[pb]; bel_x = g_arena_x[pb]; }
                    else         { bel_i = 0; bel_x = 0.0f; }
                } else {
                    have_top = false;
                }
            }
            g_arena_i[anext] = j; g_arena_x[anext] = xj; g_arena_prev[anext] = h;
            h = anext++;
            bel_i = have_top ? top_i : 0; bel_x = have_top ? top_x : 0.0f;
            top_i = j; top_x = xj; have_top = true;
        }
    }
}

// ---------------------------------------------------------------------------
// Phase C: replay each chunk seeded with its true incoming stack; writes
// exact mn[] / mj[].
// ---------------------------------------------------------------------------
__global__ void hullC_kernel(int N, int cs)
{
    int gid = blockIdx.x * blockDim.x + threadIdx.x;
    if (gid >= 2 * KCH) return;
    int side = gid / KCH;
    int c    = gid % KCH;

    int n_el;
    if (side == 0) { int s0 = 1 + c * cs; n_el = min(cs, N - s0 + 1); }
    else           { int s0 = N - c * cs; n_el = min(cs, s0); }
    if (n_el <= 0) return;

    int*   sti = g_lcl_i + (size_t)gid * CSMAX;   // reuse as phase-C local stack
    float* stx = g_lcl_x + (size_t)gid * CSMAX;
    int lcl_d = 0;
    int ah = g_snap_head[gid];
    int sentinel = (side == 0) ? 1 : N;

    int top_i = 0, bel_i = 0; float top_x = 0.0f, bel_x = 0.0f;
    bool have_top = false;
    if (ah >= 0) {
        top_i = g_arena_i[ah]; top_x = g_arena_x[ah]; have_top = true;
        int pb = g_arena_prev[ah];
        if (pb >= 0) { bel_i = g_arena_i[pb]; bel_x = g_arena_x[pb]; }
    }

    for (int p = 0; p < n_el; p++) {
        int j = (side == 0) ? (1 + c * cs + p) : (N - c * cs - p);
        float xj = XF(j);
        while (have_top && top_i != sentinel) {
            if (!pop_test(j, xj, top_i, top_x, bel_i, bel_x)) break;
            if (lcl_d > 0) lcl_d--;
            else            ah = g_arena_prev[ah];
            top_i = bel_i; top_x = bel_x;
            if (lcl_d >= 2)      { bel_i = sti[lcl_d - 2]; bel_x = stx[lcl_d - 2]; }
            else if (lcl_d == 1) { if (ah >= 0) { bel_i = g_arena_i[ah]; bel_x = g_arena_x[ah]; } }
            else if (ah >= 0) {
                int pb = g_arena_prev[ah];
                if (pb >= 0) { bel_i = g_arena_i[pb]; bel_x = g_arena_x[pb]; }
            }
            if (lcl_d == 0 && ah < 0) have_top = false;
        }
        int mnval = have_top ? top_i : j;
        if (side == 0) g_mn[j] = mnval; else g_mj[j] = mnval;
        sti[lcl_d] = j; stx[lcl_d] = xj; lcl_d++;
        bel_i = top_i; bel_x = top_x;
        top_i = j;     top_x = xj;
        have_top = true;
    }
}

// ---------------------------------------------------------------------------
// Dip kernel: single block of 1024 threads — outer loop with shared chains.
// ---------------------------------------------------------------------------
__global__ void __launch_bounds__(1024, 1) dip_kernel(int N, float* __restrict__ out)
{
    const int tid = threadIdx.x;

    __shared__ int   s_brk;
    __shared__ int   s_ig, s_lgcm, s_ih, s_llcm;
    __shared__ int   s_low, s_high;
    __shared__ float s_warp[32];
    __shared__ float s_max;
    __shared__ int   s_gi[CCAP]; __shared__ float s_gx[CCAP];
    __shared__ int   s_li[CCAP]; __shared__ float s_lx[CCAP];

    // chain accessors (1-indexed; spill to global past CCAP)
    #define GCMI(i) ((i) < CCAP ? s_gi[i] : g_gcm[i])
    #define GCMX(i) ((i) < CCAP ? s_gx[i] : g_gcm_x[i])
    #define LCMI(i) ((i) < CCAP ? s_li[i] : g_lcm[i])
    #define LCMX(i) ((i) < CCAP ? s_lx[i] : g_lcm_x[i])

    if (N < 4 || XF(1) == XF(N)) {
        if (tid == 0) out[0] = (float)(1.0 / (2.0 * (double)max(N, 1)));
        return;
    }

    int low = 1, high = N;             // thread 0 state
    double dip = 1.0;
    int ig0 = 0, ih0 = 0;
    if (tid == 0) { s_low = low; s_high = high; }

    for (int iter = 0; iter < 3000; iter++) {
        __syncthreads();   // separates prior bottom s_brk read from rewrites

        // parallel chain walks (two different warps); store (idx, x)
        if (tid == 0) {
            int i = 1, node = s_high;
            for (;;) {
                float xv = XF(node);
                if (i < CCAP) { s_gi[i] = node; s_gx[i] = xv; }
                else          { g_gcm[i] = node; g_gcm_x[i] = xv; }
                if (node <= s_low || i > N) break;
                node = g_mn[node]; i++;
            }
            s_lgcm = i;
        } else if (tid == 32) {
            int i = 1, node = s_low;
            for (;;) {
                float xv = XF(node);
                if (i < CCAP) { s_li[i] = node; s_lx[i] = xv; }
                else          { g_lcm[i] = node; g_lcm_x[i] = xv; }
                if (node >= s_high || i > N) break;
                node = g_mj[node]; i++;
            }
            s_llcm = i;
        }
        __syncthreads();

        if (tid == 0) {
            int l_gcm = s_lgcm, l_lcm = s_llcm;
            int ig = l_gcm, ix = l_gcm - 1;
            int ih = l_lcm, iv = 2;

            float d = 0.0f;
            if (l_gcm != 2 || l_lcm != 2) {
                int cap = 3 * N + 10;
                do {
                    int gcmix = GCMI(ix);
                    int lcmiv = LCMI(iv);
                    if (gcmix > lcmiv) {
                        int   gcmi1  = GCMI(ix + 1);
                        float xg     = GCMX(ix);
                        float xg1    = GCMX(ix + 1);
                        float xl     = LCMX(iv);
                        float t = ((float)(lcmiv - gcmi1) + 1.0f)
                                - (xl - xg1) * (float)(gcmix - gcmi1)
                                  / (xg - xg1);
                        iv++;
                        if (t >= d) { d = t; ig = ix + 1; ih = iv - 1; }
                    } else {
                        int   lcmiv1 = LCMI(iv - 1);
                        float xl1    = LCMX(iv - 1);
                        float xl     = LCMX(iv);
                        float xg     = GCMX(ix);
                        float t = (xg - xl1) * (float)(lcmiv - lcmiv1)
                                  / (xl - xl1)
                                - ((float)(gcmix - lcmiv1) - 1.0f);
                        ix--;
                        if (t > d) { d = t; ig = ix + 1; ih = iv; }
                    }
                    if (ix < 1) ix = 1;
                    if (iv > l_lcm) iv = l_lcm;
                } while (GCMI(ix) != LCMI(iv) && --cap > 0);
            } else {
                d = 1.0f;
            }

            if ((double)d < dip) {
                s_brk = 1;
            } else {
                s_brk = 0;
                s_ig = ig; s_ih = ih;
                ig0 = ig; ih0 = ih;
            }
        }
        __syncthreads();
        if (s_brk) break;

        // ---- fp32 segment max scans, segment-outer / block-stride inner --
        float lm = 1.0f;

        if (tid < 512) {
            for (int j = s_ig; j < s_lgcm; j++) {
                int jb = GCMI(j + 1);
                int je = GCMI(j);
                if (je - jb > 1) {
                    float xb = GCMX(j + 1), xe = GCMX(j);
                    if (xe != xb) {
                        float C = (float)(je - jb) / (xe - xb);
                        for (int pos = jb + tid; pos <= je; pos += 512) {
                            float t = (float)(pos - jb + 1) - (XF(pos) - xb) * C;
                            lm = fmaxf(lm, t);
                        }
                    }
                }
            }
        } else {
            int t2 = tid - 512;
            for (int j = s_ih; j < s_llcm; j++) {
                int jb = LCMI(j);
                int je = LCMI(j + 1);
                if (je - jb > 1) {
                    float xb = LCMX(j), xe = LCMX(j + 1);
                    if (xe != xb) {
                        float C = (float)(je - jb) / (xe - xb);
                        for (int pos = jb + t2; pos <= je; pos += 512) {
                            float t = (XF(pos) - xb) * C - ((float)(pos - jb) - 1.0f);
                            lm = fmaxf(lm, t);
                        }
                    }
                }
            }
        }

        // ---- shuffle max reduce ----
        #pragma unroll
        for (int o = 16; o > 0; o >>= 1)
            lm = fmaxf(lm, __shfl_xor_sync(0xFFFFFFFFu, lm, o));
        if ((tid & 31) == 0) s_warp[tid >> 5] = lm;
        __syncthreads();
        if (tid < 32) {
            float v = s_warp[tid];
            #pragma unroll
            for (int o = 16; o > 0; o >>= 1)
                v = fmaxf(v, __shfl_xor_sync(0xFFFFFFFFu, v, o));
            if (tid == 0) s_max = v;
        }
        __syncthreads();

        if (tid == 0) {
            double dip_new = (double)s_max;
            if (dip < dip_new) dip = dip_new;
            int nlow = GCMI(ig0), nhigh = LCMI(ih0);
            if (low == nlow && high == nhigh) {
                s_brk = 1;
            } else {
                s_brk = 0;
                low = nlow; high = nhigh;
                s_low = low; s_high = high;
            }
        }
        __syncthreads();
        if (s_brk) break;
    }

    if (tid == 0) out[0] = (float)(dip / (2.0 * (double)N));

    #undef GCMI
    #undef GCMX
    #undef LCMI
    #undef LCMX
}

// ---------------------------------------------------------------------------
// Launch: pure kernel launches, no runtime API calls.
// ---------------------------------------------------------------------------
extern "C" void kernel_launch(void* const* d_in, const int* in_sizes, int n_in,
                              void* d_out, int out_size)
{
    const float* X   = (const float*)d_in[0];
    const float* PV  = (const float*)d_in[1];
    const int*   idx = (const int*)d_in[2];
    float*       out = (float*)d_out;

    const int D = 128;
    const int N = in_sizes[0] / D;
    const int cs = (N + KCH - 1) / KCH;

    // 1. projection + pad
    matvec_kernel<<<(N + 7) / 8, 256>>>(X, PV, idx, N, D);
    pad_kernel<<<(MAXN - N + 255) / 256, 256>>>(N);

    // 2. bitonic sort (in place on g_proj), tile = 8192
    bitonic_presort_kernel<<<MAXN / TILE, 1024>>>();
    for (int size = 2 * TILE; size <= MAXN; size <<= 1) {
        for (int s = size >> 1; s >= TILE; s >>= 1)
            bitonic_global_kernel<<<(MAXN / 2) / 256, 256>>>(size, s);
        bitonic_merge_shared_kernel<<<MAXN / TILE, 1024>>>(size);
    }

    // 3. parallel hull-pointer build (mn / mj)
    hullA_kernel<<<(2 * KCH + 63) / 64, 64>>>(N, cs);
    mergeM1_kernel<<<1, 64>>>();
    mergeM2_kernel<<<1, 64>>>();
    mergeM3_kernel<<<1, 64>>>(N);
    hullC_kernel<<<(2 * KCH + 63) / 64, 64>>>(N, cs);

    // 4. dip outer loop
    dip_kernel<<<1, 1024>>>(N, out);
}

// round 11
// speedup vs baseline: 49.6196x; 1.5057x over previous
#include <cuda_runtime.h>
#include <cuda_bf16.h>
#include <math_constants.h>

// ---------------------------------------------------------------------------
// Dip statistic of a projected sample. 3-launch pipeline:
//   K1: fused matvec + pad (+ barrier-state reset)
//   K2: mega-kernel (grid-synced, 32 blocks): presort + bitonic stages +
//       hull phases A, M1, M2, M3, C
//   K3: dip outer loop (single block, shared-memory chains)
// Output: dip/(2N) as float32 scalar.
// ---------------------------------------------------------------------------

#define MAXN  (1 << 18)   // 262144 >= N = 200000
#define KCH   512         // chunks per side
#define CSMAX 512         // max chunk size
#define GRP   32          // groups per side
#define CPG   16          // chunks per group
#define GSMAX (CPG * CSMAX)
#define ARENA_M2 (GRP * GSMAX)
#define ARENA_PS (ARENA_M2 + KCH * CSMAX)
#define TILE  8192
#define CCAP  2048
#define NBLK  32          // mega-kernel blocks (co-resident, 1/SM)
#define NTHT  (NBLK * 1024)

__device__ float g_proj[MAXN];
__device__ int   g_mn[MAXN + 2];
__device__ int   g_mj[MAXN + 2];
__device__ int   g_gcm[MAXN + 2];
__device__ float g_gcm_x[MAXN + 2];
__device__ int   g_lcm[MAXN + 2];
__device__ float g_lcm_x[MAXN + 2];
__device__ int   g_lcl_i[2 * KCH * CSMAX];
__device__ float g_lcl_x[2 * KCH * CSMAX];
__device__ int   g_nsurv[2 * KCH];
__device__ int   g_grp_i[2 * GRP * GSMAX];
__device__ float g_grp_x[2 * GRP * GSMAX];
__device__ int   g_ngrp[2 * GRP];
__device__ int   g_arena_i[2 * ARENA_PS];
__device__ float g_arena_x[2 * ARENA_PS];
__device__ int   g_arena_prev[2 * ARENA_PS];
__device__ int   g_snapG[2 * GRP];
__device__ int   g_snap_head[2 * KCH];
// grid barrier state (reset by K1 every replay — corruption cannot persist)
__device__ volatile unsigned g_bar_gen;
__device__ unsigned g_bar_cnt;

#define XF(i) g_proj[(i) - 1]

// ---------------------------------------------------------------------------
// K1: fused matvec (warp per row) + pad + barrier reset
// ---------------------------------------------------------------------------
__global__ void matvec_pad_kernel(const float* __restrict__ X,
                                  const float* __restrict__ PV,
                                  const int*   __restrict__ idx,
                                  int N, int D)
{
    int gtid = blockIdx.x * blockDim.x + threadIdx.x;
    if (gtid == 0) { g_bar_gen = 0; g_bar_cnt = 0; }   // pristine barrier state
    // pad duty: first (MAXN - N) threads
    if (gtid < MAXN - N) g_proj[N + gtid] = CUDART_INF_F;

    int warp = gtid >> 5;
    int lane = gtid & 31;
    if (warp >= N) return;

    const float* p = PV + (size_t)(*idx) * D;
    const float4* row = reinterpret_cast<const float4*>(X + (size_t)warp * D);
    const float4* p4  = reinterpret_cast<const float4*>(p);

    float4 a = row[lane];
    float4 b = p4[lane];
    float s = fmaf(a.x, b.x, fmaf(a.y, b.y, fmaf(a.z, b.z, a.w * b.w)));

    #pragma unroll
    for (int o = 16; o > 0; o >>= 1)
        s += __shfl_xor_sync(0xFFFFFFFFu, s, o);

    if (lane == 0) g_proj[warp] = s;
}

// ---------------------------------------------------------------------------
// helpers
// ---------------------------------------------------------------------------
__device__ __forceinline__ void cmpxchg(float& a, float& b, bool up)
{
    if (up ? (a > b) : (a < b)) { float t = a; a = b; b = t; }
}

__device__ __forceinline__ bool pop_test(int a, float xa, int m, float xm,
                                         int mm, float xmm)
{
    float f1 = (xa - xm) * (float)(m - mm);
    float f2 = (xm - xmm) * (float)(a - m);
    float diff = f1 - f2;
    float margin = 1e-5f * (fabsf(f1) + fabsf(f2)) + 1e-30f;
    if (diff >  margin) return true;
    if (diff < -margin) return false;
    double p1 = ((double)xa - (double)xm) * (double)(m - mm);
    double p2 = ((double)xm - (double)xmm) * (double)(a - m);
    return p1 >= p2;
}

// grid barrier: fence-arrive / spin-acquire; all NBLK blocks co-resident.
__device__ __forceinline__ void grid_bar()
{
    __syncthreads();
    if (threadIdx.x == 0) {
        unsigned gen = g_bar_gen;
        __threadfence();
        if (atomicAdd(&g_bar_cnt, 1u) == NBLK - 1) {
            atomicExch(&g_bar_cnt, 0u);
            __threadfence();
            g_bar_gen = gen + 1;
        } else {
            unsigned long long sp = 0;
            while (g_bar_gen == gen && ++sp < 100000000ULL) { __nanosleep(32); }
            __threadfence();
        }
    }
    __syncthreads();
}

// ---------------------------------------------------------------------------
// K2: mega kernel — presort, bitonic stages, hull phases. 32 blocks x 1024.
// ---------------------------------------------------------------------------
__global__ void __launch_bounds__(1024, 1) mega_kernel(int N, int cs)
{
    __shared__ float sh[TILE];
    const int tid  = threadIdx.x;
    const int b    = blockIdx.x;
    const int gtid = b * 1024 + tid;
    const int w    = tid >> 5;
    const int lane = tid & 31;

    // ---- presort: block b sorts tile b (8192 elems) ----
    {
        int base = b * TILE;
        #pragma unroll
        for (int v = 0; v < TILE / 1024; v++)
            sh[tid + v * 1024] = g_proj[base + tid + v * 1024];
        __syncthreads();

        bool asc = ((base & TILE) == 0);
        for (int size = 2; size <= TILE; size <<= 1) {
            for (int s = size >> 1; s > 0; s >>= 1) {
                #pragma unroll
                for (int v = 0; v < TILE / 2048; v++) {
                    int idx = tid + v * 1024;
                    int i = ((idx & ~(s - 1)) << 1) | (idx & (s - 1));
                    int j = i | s;
                    bool up = (((i & size) == 0) == asc);
                    float a = sh[i], c = sh[j];
                    cmpxchg(a, c, up);
                    sh[i] = a; sh[j] = c;
                }
                __syncthreads();
            }
        }
        #pragma unroll
        for (int v = 0; v < TILE / 1024; v++)
            g_proj[base + tid + v * 1024] = sh[tid + v * 1024];
    }
    grid_bar();

    // ---- bitonic stages 2*TILE .. MAXN ----
    for (int size = 2 * TILE; size <= MAXN; size <<= 1) {
        for (int s = size >> 1; s >= TILE; s >>= 1) {
            for (int p = gtid; p < MAXN / 2; p += NTHT) {
                int i = ((p & ~(s - 1)) << 1) | (p & (s - 1));
                int j = i | s;
                bool up = ((i & size) == 0);
                float a = g_proj[i], c = g_proj[j];
                cmpxchg(a, c, up);
                g_proj[i] = a; g_proj[j] = c;
            }
            grid_bar();
        }
        // merge-shared on own tile
        {
            int base = b * TILE;
            #pragma unroll
            for (int v = 0; v < TILE / 1024; v++)
                sh[tid + v * 1024] = g_proj[base + tid + v * 1024];
            __syncthreads();
            bool up = ((base & size) == 0);
            for (int s = TILE / 2; s > 0; s >>= 1) {
                #pragma unroll
                for (int v = 0; v < TILE / 2048; v++) {
                    int idx = tid + v * 1024;
                    int i = ((idx & ~(s - 1)) << 1) | (idx & (s - 1));
                    int j = i | s;
                    float a = sh[i], c = sh[j];
                    cmpxchg(a, c, up);
                    sh[i] = a; sh[j] = c;
                }
                __syncthreads();
            }
            #pragma unroll
            for (int v = 0; v < TILE / 1024; v++)
                g_proj[base + tid + v * 1024] = sh[tid + v * 1024];
        }
        grid_bar();
    }

    // ---- hull phase A: 1024 tasks, one per (warp, block), lane 0 ----
    if (lane == 0) {
        int t = w * NBLK + b;            // 0..1023
        int side = t / KCH;
        int c    = t % KCH;
        int n_el;
        if (side == 0) { int s0 = 1 + c * cs; n_el = min(cs, N - s0 + 1); }
        else           { int s0 = N - c * cs; n_el = min(cs, s0); }
        if (n_el <= 0) { g_nsurv[t] = 0; }
        else {
            int*   sti = g_lcl_i + (size_t)t * CSMAX;
            float* stx = g_lcl_x + (size_t)t * CSMAX;
            int d = 0;
            int top_i = 0, bel_i = 0; float top_x = 0.0f, bel_x = 0.0f;
            for (int p = 0; p < n_el; p++) {
                int j = (side == 0) ? (1 + c * cs + p) : (N - c * cs - p);
                float xj = XF(j);
                while (d >= 2) {
                    if (!pop_test(j, xj, top_i, top_x, bel_i, bel_x)) break;
                    d--;
                    top_i = bel_i; top_x = bel_x;
                    if (d >= 2) { bel_i = sti[d - 2]; bel_x = stx[d - 2]; }
                }
                sti[d] = j; stx[d] = xj; d++;
                bel_i = top_i; bel_x = top_x;
                top_i = j;     top_x = xj;
            }
            g_nsurv[t] = d;
        }
    }
    grid_bar();

    // ---- M1: 64 tasks ----
    if (lane == 0 && w < 2) {
        int t = w * NBLK + b;            // 0..63
        int side = t / GRP, g = t % GRP;
        int*   out_i = g_grp_i + (size_t)(side * GRP + g) * GSMAX;
        float* out_x = g_grp_x + (size_t)(side * GRP + g) * GSMAX;
        int d = 0;
        int top_i = 0, bel_i = 0; float top_x = 0.0f, bel_x = 0.0f;
        for (int k = 0; k < CPG; k++) {
            int cid = side * KCH + g * CPG + k;
            int ns = g_nsurv[cid];
            const int*   si = g_lcl_i + (size_t)cid * CSMAX;
            const float* sx = g_lcl_x + (size_t)cid * CSMAX;
            for (int q = 0; q < ns; q++) {
                int j = si[q]; float xj = sx[q];
                while (d >= 2) {
                    if (!pop_test(j, xj, top_i, top_x, bel_i, bel_x)) break;
                    d--;
                    top_i = bel_i; top_x = bel_x;
                    if (d >= 2) { bel_i = out_i[d - 2]; bel_x = out_x[d - 2]; }
                }
                out_i[d] = j; out_x[d] = xj; d++;
                bel_i = top_i; bel_x = top_x;
                top_i = j;     top_x = xj;
            }
        }
        g_ngrp[side * GRP + g] = d;
    }
    grid_bar();

    // ---- M2: 2 serial tasks on blocks 0 and 1 ----
    if (lane == 0 && w == 0 && (b == 0 || b == 1)) {
        int side = b;
        int base = side * ARENA_PS;
        int h = -1, anext = base, d = 0;
        int top_i = 0, bel_i = 0; float top_x = 0.0f, bel_x = 0.0f;
        for (int g = 0; g < GRP; g++) {
            g_snapG[side * GRP + g] = h;
            int ng = g_ngrp[side * GRP + g];
            const int*   si = g_grp_i + (size_t)(side * GRP + g) * GSMAX;
            const float* sx = g_grp_x + (size_t)(side * GRP + g) * GSMAX;
            for (int q = 0; q < ng; q++) {
                int j = si[q]; float xj = sx[q];
                while (d >= 2) {
                    if (!pop_test(j, xj, top_i, top_x, bel_i, bel_x)) break;
                    h = g_arena_prev[h];
                    d--;
                    top_i = bel_i; top_x = bel_x;
                    if (d >= 2) {
                        int pb = g_arena_prev[h];
                        bel_i = g_arena_i[pb]; bel_x = g_arena_x[pb];
                    }
                }
                g_arena_i[anext] = j; g_arena_x[anext] = xj; g_arena_prev[anext] = h;
                h = anext++; d++;
                bel_i = top_i; bel_x = top_x;
                top_i = j;     top_x = xj;
            }
        }
    }
    grid_bar();

    // ---- M3: 64 tasks ----
    if (lane == 0 && w < 2) {
        int t = w * NBLK + b;
        int side = t / GRP, g = t % GRP;
        int sentinel = (side == 0) ? 1 : N;
        int h = g_snapG[side * GRP + g];
        int anext = side * ARENA_PS + ARENA_M2 + g * GSMAX;

        int top_i = 0, bel_i = 0; float top_x = 0.0f, bel_x = 0.0f;
        bool have_top = false;
        if (h >= 0) {
            top_i = g_arena_i[h]; top_x = g_arena_x[h]; have_top = true;
            int pb = g_arena_prev[h];
            if (pb >= 0) { bel_i = g_arena_i[pb]; bel_x = g_arena_x[pb]; }
        }
        for (int k = 0; k < CPG; k++) {
            int cid = side * KCH + g * CPG + k;
            g_snap_head[cid] = h;
            int ns = g_nsurv[cid];
            const int*   si = g_lcl_i + (size_t)cid * CSMAX;
            const float* sx = g_lcl_x + (size_t)cid * CSMAX;
            for (int q = 0; q < ns; q++) {
                int j = si[q]; float xj = sx[q];
                while (have_top && top_i != sentinel) {
                    if (!pop_test(j, xj, top_i, top_x, bel_i, bel_x)) break;
                    h = g_arena_prev[h];
                    if (h >= 0) {
                        top_i = g_arena_i[h]; top_x = g_arena_x[h];
                        int pb = g_arena_prev[h];
                        if (pb >= 0) { bel_i = g_arena_i[pb]; bel_x = g_arena_x[pb]; }
                        else         { bel_i = 0; bel_x = 0.0f; }
                    } else {
                        have_top = false;
                    }
                }
                g_arena_i[anext] = j; g_arena_x[anext] = xj; g_arena_prev[anext] = h;
                h = anext++;
                bel_i = have_top ? top_i : 0; bel_x = have_top ? top_x : 0.0f;
                top_i = j; top_x = xj; have_top = true;
            }
        }
    }
    grid_bar();

    // ---- hull phase C: 1024 tasks ----
    if (lane == 0) {
        int t = w * NBLK + b;
        int side = t / KCH;
        int c    = t % KCH;
        int n_el;
        if (side == 0) { int s0 = 1 + c * cs; n_el = min(cs, N - s0 + 1); }
        else           { int s0 = N - c * cs; n_el = min(cs, s0); }
        if (n_el > 0) {
            int*   sti = g_lcl_i + (size_t)t * CSMAX;
            float* stx = g_lcl_x + (size_t)t * CSMAX;
            int lcl_d = 0;
            int ah = g_snap_head[t];
            int sentinel = (side == 0) ? 1 : N;

            int top_i = 0, bel_i = 0; float top_x = 0.0f, bel_x = 0.0f;
            bool have_top = false;
            if (ah >= 0) {
                top_i = g_arena_i[ah]; top_x = g_arena_x[ah]; have_top = true;
                int pb = g_arena_prev[ah];
                if (pb >= 0) { bel_i = g_arena_i[pb]; bel_x = g_arena_x[pb]; }
            }
            for (int p = 0; p < n_el; p++) {
                int j = (side == 0) ? (1 + c * cs + p) : (N - c * cs - p);
                float xj = XF(j);
                while (have_top && top_i != sentinel) {
                    if (!pop_test(j, xj, top_i, top_x, bel_i, bel_x)) break;
                    if (lcl_d > 0) lcl_d--;
                    else            ah = g_arena_prev[ah];
                    top_i = bel_i; top_x = bel_x;
                    if (lcl_d >= 2)      { bel_i = sti[lcl_d - 2]; bel_x = stx[lcl_d - 2]; }
                    else if (lcl_d == 1) { if (ah >= 0) { bel_i = g_arena_i[ah]; bel_x = g_arena_x[ah]; } }
                    else if (ah >= 0) {
                        int pb = g_arena_prev[ah];
                        if (pb >= 0) { bel_i = g_arena_i[pb]; bel_x = g_arena_x[pb]; }
                    }
                    if (lcl_d == 0 && ah < 0) have_top = false;
                }
                int mnval = have_top ? top_i : j;
                if (side == 0) g_mn[j] = mnval; else g_mj[j] = mnval;
                sti[lcl_d] = j; stx[lcl_d] = xj; lcl_d++;
                bel_i = top_i; bel_x = top_x;
                top_i = j;     top_x = xj;
                have_top = true;
            }
        }
    }
}

// ---------------------------------------------------------------------------
// K3: dip outer loop (single block of 1024, shared chains).
// ---------------------------------------------------------------------------
__global__ void __launch_bounds__(1024, 1) dip_kernel(int N, float* __restrict__ out)
{
    const int tid = threadIdx.x;

    __shared__ int   s_brk;
    __shared__ int   s_ig, s_lgcm, s_ih, s_llcm;
    __shared__ int   s_low, s_high;
    __shared__ float s_warp[32];
    __shared__ float s_max;
    __shared__ int   s_gi[CCAP]; __shared__ float s_gx[CCAP];
    __shared__ int   s_li[CCAP]; __shared__ float s_lx[CCAP];

    #define GCMI(i) ((i) < CCAP ? s_gi[i] : g_gcm[i])
    #define GCMX(i) ((i) < CCAP ? s_gx[i] : g_gcm_x[i])
    #define LCMI(i) ((i) < CCAP ? s_li[i] : g_lcm[i])
    #define LCMX(i) ((i) < CCAP ? s_lx[i] : g_lcm_x[i])

    if (N < 4 || XF(1) == XF(N)) {
        if (tid == 0) out[0] = (float)(1.0 / (2.0 * (double)max(N, 1)));
        return;
    }

    int low = 1, high = N;
    double dip = 1.0;
    int ig0 = 0, ih0 = 0;
    if (tid == 0) { s_low = low; s_high = high; }

    for (int iter = 0; iter < 3000; iter++) {
        __syncthreads();

        if (tid == 0) {
            int i = 1, node = s_high;
            for (;;) {
                float xv = XF(node);
                if (i < CCAP) { s_gi[i] = node; s_gx[i] = xv; }
                else          { g_gcm[i] = node; g_gcm_x[i] = xv; }
                if (node <= s_low || i > N) break;
                node = g_mn[node]; i++;
            }
            s_lgcm = i;
        } else if (tid == 32) {
            int i = 1, node = s_low;
            for (;;) {
                float xv = XF(node);
                if (i < CCAP) { s_li[i] = node; s_lx[i] = xv; }
                else          { g_lcm[i] = node; g_lcm_x[i] = xv; }
                if (node >= s_high || i > N) break;
                node = g_mj[node]; i++;
            }
            s_llcm = i;
        }
        __syncthreads();

        if (tid == 0) {
            int l_gcm = s_lgcm, l_lcm = s_llcm;
            int ig = l_gcm, ix = l_gcm - 1;
            int ih = l_lcm, iv = 2;

            float d = 0.0f;
            if (l_gcm != 2 || l_lcm != 2) {
                int cap = 3 * N + 10;
                do {
                    int gcmix = GCMI(ix);
                    int lcmiv = LCMI(iv);
                    if (gcmix > lcmiv) {
                        int   gcmi1 = GCMI(ix + 1);
                        float xg  = GCMX(ix);
                        float xg1 = GCMX(ix + 1);
                        float xl  = LCMX(iv);
                        float t = ((float)(lcmiv - gcmi1) + 1.0f)
                                - (xl - xg1) * (float)(gcmix - gcmi1) / (xg - xg1);
                        iv++;
                        if (t >= d) { d = t; ig = ix + 1; ih = iv - 1; }
                    } else {
                        int   lcmiv1 = LCMI(iv - 1);
                        float xl1 = LCMX(iv - 1);
                        float xl  = LCMX(iv);
                        float xg  = GCMX(ix);
                        float t = (xg - xl1) * (float)(lcmiv - lcmiv1) / (xl - xl1)
                                - ((float)(gcmix - lcmiv1) - 1.0f);
                        ix--;
                        if (t > d) { d = t; ig = ix + 1; ih = iv; }
                    }
                    if (ix < 1) ix = 1;
                    if (iv > l_lcm) iv = l_lcm;
                } while (GCMI(ix) != LCMI(iv) && --cap > 0);
            } else {
                d = 1.0f;
            }

            if ((double)d < dip) {
                s_brk = 1;
            } else {
                s_brk = 0;
                s_ig = ig; s_ih = ih;
                ig0 = ig; ih0 = ih;
            }
        }
        __syncthreads();
        if (s_brk) break;

        float lm = 1.0f;
        if (tid < 512) {
            for (int j = s_ig; j < s_lgcm; j++) {
                int jb = GCMI(j + 1);
                int je = GCMI(j);
                if (je - jb > 1) {
                    float xb = GCMX(j + 1), xe = GCMX(j);
                    if (xe != xb) {
                        float C = (float)(je - jb) / (xe - xb);
                        for (int pos = jb + tid; pos <= je; pos += 512) {
                            float t = (float)(pos - jb + 1) - (XF(pos) - xb) * C;
                            lm = fmaxf(lm, t);
                        }
                    }
                }
            }
        } else {
            int t2 = tid - 512;
            for (int j = s_ih; j < s_llcm; j++) {
                int jb = LCMI(j);
                int je = LCMI(j + 1);
                if (je - jb > 1) {
                    float xb = LCMX(j), xe = LCMX(j + 1);
                    if (xe != xb) {
                        float C = (float)(je - jb) / (xe - xb);
                        for (int pos = jb + t2; pos <= je; pos += 512) {
                            float t = (XF(pos) - xb) * C - ((float)(pos - jb) - 1.0f);
                            lm = fmaxf(lm, t);
                        }
                    }
                }
            }
        }

        #pragma unroll
        for (int o = 16; o > 0; o >>= 1)
            lm = fmaxf(lm, __shfl_xor_sync(0xFFFFFFFFu, lm, o));
        if ((tid & 31) == 0) s_warp[tid >> 5] = lm;
        __syncthreads();
        if (tid < 32) {
            float v = s_warp[tid];
            #pragma unroll
            for (int o = 16; o > 0; o >>= 1)
                v = fmaxf(v, __shfl_xor_sync(0xFFFFFFFFu, v, o));
            if (tid == 0) s_max = v;
        }
        __syncthreads();

        if (tid == 0) {
            double dip_new = (double)s_max;
            if (dip < dip_new) dip = dip_new;
            int nlow = GCMI(ig0), nhigh = LCMI(ih0);
            if (low == nlow && high == nhigh) {
                s_brk = 1;
            } else {
                s_brk = 0;
                low = nlow; high = nhigh;
                s_low = low; s_high = high;
            }
        }
        __syncthreads();
        if (s_brk) break;
    }

    if (tid == 0) out[0] = (float)(dip / (2.0 * (double)N));

    #undef GCMI
    #undef GCMX
    #undef LCMI
    #undef LCMX
}

// ---------------------------------------------------------------------------
// Launch: 3 kernels.
// ---------------------------------------------------------------------------
extern "C" void kernel_launch(void* const* d_in, const int* in_sizes, int n_in,
                              void* d_out, int out_size)
{
    const float* X   = (const float*)d_in[0];
    const float* PV  = (const float*)d_in[1];
    const int*   idx = (const int*)d_in[2];
    float*       out = (float*)d_out;

    const int D = 128;
    const int N = in_sizes[0] / D;
    const int cs = (N + KCH - 1) / KCH;

    matvec_pad_kernel<<<(N * 32 + 255) / 256, 256>>>(X, PV, idx, N, D);
    mega_kernel<<<NBLK, 1024>>>(N, cs);
    dip_kernel<<<1, 1024>>>(N, out);
}

// round 12
// speedup vs baseline: 49.6551x; 1.0007x over previous
#include <cuda_runtime.h>
#include <cuda_bf16.h>
#include <math_constants.h>

// ---------------------------------------------------------------------------
// Dip statistic of a projected sample. 4-launch pipeline:
//   K1: fused matvec (2 rows/warp) + pad + barrier resets
//   K2: sort_kernel (grid-synced, 32 blocks): presort + bitonic stages
//   K3: hull_kernel (grid-synced, 32 blocks): phases A, M1, M2, M3, C
//   K4: dip outer loop (single block, shared-memory chains)
// Output: dip/(2N) as float32 scalar.
// ---------------------------------------------------------------------------

#define MAXN  (1 << 18)   // 262144 >= N = 200000
#define KCH   512         // chunks per side
#define CSMAX 512         // max chunk size
#define GRP   32          // groups per side
#define CPG   16          // chunks per group
#define GSMAX (CPG * CSMAX)
#define ARENA_M2 (GRP * GSMAX)
#define ARENA_PS (ARENA_M2 + KCH * CSMAX)
#define TILE  8192
#define CCAP  2048
#define NBLK  32          // grid-synced kernels: blocks (co-resident, 1/SM)
#define NTHT  (NBLK * 1024)

__device__ float g_proj[MAXN];
__device__ int   g_mn[MAXN + 2];
__device__ int   g_mj[MAXN + 2];
__device__ int   g_gcm[MAXN + 2];
__device__ float g_gcm_x[MAXN + 2];
__device__ int   g_lcm[MAXN + 2];
__device__ float g_lcm_x[MAXN + 2];
__device__ int   g_lcl_i[2 * KCH * CSMAX];
__device__ float g_lcl_x[2 * KCH * CSMAX];
__device__ int   g_nsurv[2 * KCH];
__device__ int   g_grp_i[2 * GRP * GSMAX];
__device__ float g_grp_x[2 * GRP * GSMAX];
__device__ int   g_ngrp[2 * GRP];
__device__ int   g_arena_i[2 * ARENA_PS];
__device__ float g_arena_x[2 * ARENA_PS];
__device__ int   g_arena_prev[2 * ARENA_PS];
__device__ int   g_snapG[2 * GRP];
__device__ int   g_snap_head[2 * KCH];
// grid barrier state (two independent pairs; reset by K1 every replay)
__device__ volatile unsigned g_barA_gen;
__device__ unsigned g_barA_cnt;
__device__ volatile unsigned g_barB_gen;
__device__ unsigned g_barB_cnt;

#define XF(i) g_proj[(i) - 1]

// ---------------------------------------------------------------------------
// K1: fused matvec (2 rows per warp) + pad + barrier resets
// ---------------------------------------------------------------------------
__global__ void matvec_pad_kernel(const float* __restrict__ X,
                                  const float* __restrict__ PV,
                                  const int*   __restrict__ idx,
                                  int N, int D)
{
    int gtid = blockIdx.x * blockDim.x + threadIdx.x;
    if (gtid == 0) {
        g_barA_gen = 0; g_barA_cnt = 0;
        g_barB_gen = 0; g_barB_cnt = 0;
    }
    // pad duty
    if (gtid < MAXN - N) g_proj[N + gtid] = CUDART_INF_F;

    int warp = gtid >> 5;
    int lane = gtid & 31;
    int r0 = warp * 2;
    int r1 = r0 + 1;
    if (r0 >= N) return;

    const float* p = PV + (size_t)(*idx) * D;
    const float4* p4 = reinterpret_cast<const float4*>(p);
    float4 b = p4[lane];

    const float4* row0 = reinterpret_cast<const float4*>(X + (size_t)r0 * D);
    float4 a0 = row0[lane];
    float s0 = fmaf(a0.x, b.x, fmaf(a0.y, b.y, fmaf(a0.z, b.z, a0.w * b.w)));

    float s1 = 0.0f;
    if (r1 < N) {
        const float4* row1 = reinterpret_cast<const float4*>(X + (size_t)r1 * D);
        float4 a1 = row1[lane];
        s1 = fmaf(a1.x, b.x, fmaf(a1.y, b.y, fmaf(a1.z, b.z, a1.w * b.w)));
    }

    #pragma unroll
    for (int o = 16; o > 0; o >>= 1) {
        s0 += __shfl_xor_sync(0xFFFFFFFFu, s0, o);
        s1 += __shfl_xor_sync(0xFFFFFFFFu, s1, o);
    }

    if (lane == 0) {
        g_proj[r0] = s0;
        if (r1 < N) g_proj[r1] = s1;
    }
}

// ---------------------------------------------------------------------------
// helpers
// ---------------------------------------------------------------------------
__device__ __forceinline__ void cmpxchg(float& a, float& b, bool up)
{
    if (up ? (a > b) : (a < b)) { float t = a; a = b; b = t; }
}

__device__ __forceinline__ bool pop_test(int a, float xa, int m, float xm,
                                         int mm, float xmm)
{
    float f1 = (xa - xm) * (float)(m - mm);
    float f2 = (xm - xmm) * (float)(a - m);
    float diff = f1 - f2;
    float margin = 1e-5f * (fabsf(f1) + fabsf(f2)) + 1e-30f;
    if (diff >  margin) return true;
    if (diff < -margin) return false;
    double p1 = ((double)xa - (double)xm) * (double)(m - mm);
    double p2 = ((double)xm - (double)xmm) * (double)(a - m);
    return p1 >= p2;
}

// grid barrier (pair select by template arg); plain spin, capped.
template <int PAIR>
__device__ __forceinline__ void grid_bar()
{
    __syncthreads();
    if (threadIdx.x == 0) {
        if (PAIR == 0) {
            unsigned gen = g_barA_gen;
            __threadfence();
            if (atomicAdd(&g_barA_cnt, 1u) == NBLK - 1) {
                atomicExch(&g_barA_cnt, 0u);
                __threadfence();
                g_barA_gen = gen + 1;
            } else {
                unsigned long long sp = 0;
                while (g_barA_gen == gen && ++sp < 20000000ULL) {}
                __threadfence();
            }
        } else {
            unsigned gen = g_barB_gen;
            __threadfence();
            if (atomicAdd(&g_barB_cnt, 1u) == NBLK - 1) {
                atomicExch(&g_barB_cnt, 0u);
                __threadfence();
                g_barB_gen = gen + 1;
            } else {
                unsigned long long sp = 0;
                while (g_barB_gen == gen && ++sp < 20000000ULL) {}
                __threadfence();
            }
        }
    }
    __syncthreads();
}

// ---------------------------------------------------------------------------
// K2: sort kernel — presort + bitonic stages. 32 blocks x 1024.
// ---------------------------------------------------------------------------
__global__ void __launch_bounds__(1024, 1) sort_kernel()
{
    __shared__ float sh[TILE];
    const int tid  = threadIdx.x;
    const int b    = blockIdx.x;
    const int gtid = b * 1024 + tid;

    // ---- presort: block b sorts tile b ----
    {
        int base = b * TILE;
        #pragma unroll
        for (int v = 0; v < TILE / 1024; v++)
            sh[tid + v * 1024] = g_proj[base + tid + v * 1024];
        __syncthreads();

        bool asc = ((base & TILE) == 0);
        for (int size = 2; size <= TILE; size <<= 1) {
            for (int s = size >> 1; s > 0; s >>= 1) {
                #pragma unroll
                for (int v = 0; v < TILE / 2048; v++) {
                    int idx = tid + v * 1024;
                    int i = ((idx & ~(s - 1)) << 1) | (idx & (s - 1));
                    int j = i | s;
                    bool up = (((i & size) == 0) == asc);
                    float a = sh[i], c = sh[j];
                    cmpxchg(a, c, up);
                    sh[i] = a; sh[j] = c;
                }
                __syncthreads();
            }
        }
        #pragma unroll
        for (int v = 0; v < TILE / 1024; v++)
            g_proj[base + tid + v * 1024] = sh[tid + v * 1024];
    }
    grid_bar<0>();

    // ---- bitonic stages ----
    for (int size = 2 * TILE; size <= MAXN; size <<= 1) {
        for (int s = size >> 1; s >= TILE; s >>= 1) {
            for (int p = gtid; p < MAXN / 2; p += NTHT) {
                int i = ((p & ~(s - 1)) << 1) | (p & (s - 1));
                int j = i | s;
                bool up = ((i & size) == 0);
                float a = g_proj[i], c = g_proj[j];
                cmpxchg(a, c, up);
                g_proj[i] = a; g_proj[j] = c;
            }
            grid_bar<0>();
        }
        // merge-shared on own tile
        {
            int base = b * TILE;
            #pragma unroll
            for (int v = 0; v < TILE / 1024; v++)
                sh[tid + v * 1024] = g_proj[base + tid + v * 1024];
            __syncthreads();
            bool up = ((base & size) == 0);
            for (int s = TILE / 2; s > 0; s >>= 1) {
                #pragma unroll
                for (int v = 0; v < TILE / 2048; v++) {
                    int idx = tid + v * 1024;
                    int i = ((idx & ~(s - 1)) << 1) | (idx & (s - 1));
                    int j = i | s;
                    float a = sh[i], c = sh[j];
                    cmpxchg(a, c, up);
                    sh[i] = a; sh[j] = c;
                }
                __syncthreads();
            }
            #pragma unroll
            for (int v = 0; v < TILE / 1024; v++)
                g_proj[base + tid + v * 1024] = sh[tid + v * 1024];
        }
        if (size < MAXN) grid_bar<0>();
    }
}

// ---------------------------------------------------------------------------
// K3: hull kernel — phases A, M1, M2, M3, C. 32 blocks x 1024.
// ---------------------------------------------------------------------------
__global__ void __launch_bounds__(1024, 1) hull_kernel(int N, int cs)
{
    const int tid  = threadIdx.x;
    const int b    = blockIdx.x;
    const int w    = tid >> 5;
    const int lane = tid & 31;

    // ---- phase A: 1024 tasks, one per (warp, block), lane 0 ----
    if (lane == 0) {
        int t = w * NBLK + b;
        int side = t / KCH;
        int c    = t % KCH;
        int n_el;
        if (side == 0) { int s0 = 1 + c * cs; n_el = min(cs, N - s0 + 1); }
        else           { int s0 = N - c * cs; n_el = min(cs, s0); }
        if (n_el <= 0) { g_nsurv[t] = 0; }
        else {
            int*   sti = g_lcl_i + (size_t)t * CSMAX;
            float* stx = g_lcl_x + (size_t)t * CSMAX;
            int d = 0;
            int top_i = 0, bel_i = 0; float top_x = 0.0f, bel_x = 0.0f;
            for (int p = 0; p < n_el; p++) {
                int j = (side == 0) ? (1 + c * cs + p) : (N - c * cs - p);
                float xj = XF(j);
                while (d >= 2) {
                    if (!pop_test(j, xj, top_i, top_x, bel_i, bel_x)) break;
                    d--;
                    top_i = bel_i; top_x = bel_x;
                    if (d >= 2) { bel_i = sti[d - 2]; bel_x = stx[d - 2]; }
                }
                sti[d] = j; stx[d] = xj; d++;
                bel_i = top_i; bel_x = top_x;
                top_i = j;     top_x = xj;
            }
            g_nsurv[t] = d;
        }
    }
    grid_bar<1>();

    // ---- M1: 64 tasks ----
    if (lane == 0 && w < 2) {
        int t = w * NBLK + b;
        int side = t / GRP, g = t % GRP;
        int*   out_i = g_grp_i + (size_t)(side * GRP + g) * GSMAX;
        float* out_x = g_grp_x + (size_t)(side * GRP + g) * GSMAX;
        int d = 0;
        int top_i = 0, bel_i = 0; float top_x = 0.0f, bel_x = 0.0f;
        for (int k = 0; k < CPG; k++) {
            int cid = side * KCH + g * CPG + k;
            int ns = g_nsurv[cid];
            const int*   si = g_lcl_i + (size_t)cid * CSMAX;
            const float* sx = g_lcl_x + (size_t)cid * CSMAX;
            for (int q = 0; q < ns; q++) {
                int j = si[q]; float xj = sx[q];
                while (d >= 2) {
                    if (!pop_test(j, xj, top_i, top_x, bel_i, bel_x)) break;
                    d--;
                    top_i = bel_i; top_x = bel_x;
                    if (d >= 2) { bel_i = out_i[d - 2]; bel_x = out_x[d - 2]; }
                }
                out_i[d] = j; out_x[d] = xj; d++;
                bel_i = top_i; bel_x = top_x;
                top_i = j;     top_x = xj;
            }
        }
        g_ngrp[side * GRP + g] = d;
    }
    grid_bar<1>();

    // ---- M2: 2 serial tasks on blocks 0 and 1 ----
    if (lane == 0 && w == 0 && (b == 0 || b == 1)) {
        int side = b;
        int base = side * ARENA_PS;
        int h = -1, anext = base, d = 0;
        int top_i = 0, bel_i = 0; float top_x = 0.0f, bel_x = 0.0f;
        for (int g = 0; g < GRP; g++) {
            g_snapG[side * GRP + g] = h;
            int ng = g_ngrp[side * GRP + g];
            const int*   si = g_grp_i + (size_t)(side * GRP + g) * GSMAX;
            const float* sx = g_grp_x + (size_t)(side * GRP + g) * GSMAX;
            for (int q = 0; q < ng; q++) {
                int j = si[q]; float xj = sx[q];
                while (d >= 2) {
                    if (!pop_test(j, xj, top_i, top_x, bel_i, bel_x)) break;
                    h = g_arena_prev[h];
                    d--;
                    top_i = bel_i; top_x = bel_x;
                    if (d >= 2) {
                        int pb = g_arena_prev[h];
                        bel_i = g_arena_i[pb]; bel_x = g_arena_x[pb];
                    }
                }
                g_arena_i[anext] = j; g_arena_x[anext] = xj; g_arena_prev[anext] = h;
                h = anext++; d++;
                bel_i = top_i; bel_x = top_x;
                top_i = j;     top_x = xj;
            }
        }
    }
    grid_bar<1>();

    // ---- M3: 64 tasks ----
    if (lane == 0 && w < 2) {
        int t = w * NBLK + b;
        int side = t / GRP, g = t % GRP;
        int sentinel = (side == 0) ? 1 : N;
        int h = g_snapG[side * GRP + g];
        int anext = side * ARENA_PS + ARENA_M2 + g * GSMAX;

        int top_i = 0, bel_i = 0; float top_x = 0.0f, bel_x = 0.0f;
        bool have_top = false;
        if (h >= 0) {
            top_i = g_arena_i[h]; top_x = g_arena_x[h]; have_top = true;
            int pb = g_arena_prev[h];
            if (pb >= 0) { bel_i = g_arena_i[pb]; bel_x = g_arena_x[pb]; }
        }
        for (int k = 0; k < CPG; k++) {
            int cid = side * KCH + g * CPG + k;
            g_snap_head[cid] = h;
            int ns = g_nsurv[cid];
            const int*   si = g_lcl_i + (size_t)cid * CSMAX;
            const float* sx = g_lcl_x + (size_t)cid * CSMAX;
            for (int q = 0; q < ns; q++) {
                int j = si[q]; float xj = sx[q];
                while (have_top && top_i != sentinel) {
                    if (!pop_test(j, xj, top_i, top_x, bel_i, bel_x)) break;
                    h = g_arena_prev[h];
                    if (h >= 0) {
                        top_i = g_arena_i[h]; top_x = g_arena_x[h];
                        int pb = g_arena_prev[h];
                        if (pb >= 0) { bel_i = g_arena_i[pb]; bel_x = g_arena_x[pb]; }
                        else         { bel_i = 0; bel_x = 0.0f; }
                    } else {
                        have_top = false;
                    }
                }
                g_arena_i[anext] = j; g_arena_x[anext] = xj; g_arena_prev[anext] = h;
                h = anext++;
                bel_i = have_top ? top_i : 0; bel_x = have_top ? top_x : 0.0f;
                top_i = j; top_x = xj; have_top = true;
            }
        }
    }
    grid_bar<1>();

    // ---- phase C: 1024 tasks ----
    if (lane == 0) {
        int t = w * NBLK + b;
        int side = t / KCH;
        int c    = t % KCH;
        int n_el;
        if (side == 0) { int s0 = 1 + c * cs; n_el = min(cs, N - s0 + 1); }
        else           { int s0 = N - c * cs; n_el = min(cs, s0); }
        if (n_el > 0) {
            int*   sti = g_lcl_i + (size_t)t * CSMAX;
            float* stx = g_lcl_x + (size_t)t * CSMAX;
            int lcl_d = 0;
            int ah = g_snap_head[t];
            int sentinel = (side == 0) ? 1 : N;

            int top_i = 0, bel_i = 0; float top_x = 0.0f, bel_x = 0.0f;
            bool have_top = false;
            if (ah >= 0) {
                top_i = g_arena_i[ah]; top_x = g_arena_x[ah]; have_top = true;
                int pb = g_arena_prev[ah];
                if (pb >= 0) { bel_i = g_arena_i[pb]; bel_x = g_arena_x[pb]; }
            }
            for (int p = 0; p < n_el; p++) {
                int j = (side == 0) ? (1 + c * cs + p) : (N - c * cs - p);
                float xj = XF(j);
                while (have_top && top_i != sentinel) {
                    if (!pop_test(j, xj, top_i, top_x, bel_i, bel_x)) break;
                    if (lcl_d > 0) lcl_d--;
                    else            ah = g_arena_prev[ah];
                    top_i = bel_i; top_x = bel_x;
                    if (lcl_d >= 2)      { bel_i = sti[lcl_d - 2]; bel_x = stx[lcl_d - 2]; }
                    else if (lcl_d == 1) { if (ah >= 0) { bel_i = g_arena_i[ah]; bel_x = g_arena_x[ah]; } }
                    else if (ah >= 0) {
                        int pb = g_arena_prev[ah];
                        if (pb >= 0) { bel_i = g_arena_i[pb]; bel_x = g_arena_x[pb]; }
                    }
                    if (lcl_d == 0 && ah < 0) have_top = false;
                }
                int mnval = have_top ? top_i : j;
                if (side == 0) g_mn[j] = mnval; else g_mj[j] = mnval;
                sti[lcl_d] = j; stx[lcl_d] = xj; lcl_d++;
                bel_i = top_i; bel_x = top_x;
                top_i = j;     top_x = xj;
                have_top = true;
            }
        }
    }
}

// ---------------------------------------------------------------------------
// K4: dip outer loop (single block of 1024, shared chains).
// ---------------------------------------------------------------------------
__global__ void __launch_bounds__(1024, 1) dip_kernel(int N, float* __restrict__ out)
{
    const int tid = threadIdx.x;

    __shared__ int   s_brk;
    __shared__ int   s_ig, s_lgcm, s_ih, s_llcm;
    __shared__ int   s_low, s_high;
    __shared__ float s_warp[32];
    __shared__ float s_max;
    __shared__ int   s_gi[CCAP]; __shared__ float s_gx[CCAP];
    __shared__ int   s_li[CCAP]; __shared__ float s_lx[CCAP];

    #define GCMI(i) ((i) < CCAP ? s_gi[i] : g_gcm[i])
    #define GCMX(i) ((i) < CCAP ? s_gx[i] : g_gcm_x[i])
    #define LCMI(i) ((i) < CCAP ? s_li[i] : g_lcm[i])
    #define LCMX(i) ((i) < CCAP ? s_lx[i] : g_lcm_x[i])

    if (N < 4 || XF(1) == XF(N)) {
        if (tid == 0) out[0] = (float)(1.0 / (2.0 * (double)max(N, 1)));
        return;
    }

    int low = 1, high = N;
    double dip = 1.0;
    int ig0 = 0, ih0 = 0;
    if (tid == 0) { s_low = low; s_high = high; }

    for (int iter = 0; iter < 3000; iter++) {
        __syncthreads();

        if (tid == 0) {
            int i = 1, node = s_high;
            for (;;) {
                float xv = XF(node);
                if (i < CCAP) { s_gi[i] = node; s_gx[i] = xv; }
                else          { g_gcm[i] = node; g_gcm_x[i] = xv; }
                if (node <= s_low || i > N) break;
                node = g_mn[node]; i++;
            }
            s_lgcm = i;
        } else if (tid == 32) {
            int i = 1, node = s_low;
            for (;;) {
                float xv = XF(node);
                if (i < CCAP) { s_li[i] = node; s_lx[i] = xv; }
                else          { g_lcm[i] = node; g_lcm_x[i] = xv; }
                if (node >= s_high || i > N) break;
                node = g_mj[node]; i++;
            }
            s_llcm = i;
        }
        __syncthreads();

        if (tid == 0) {
            int l_gcm = s_lgcm, l_lcm = s_llcm;
            int ig = l_gcm, ix = l_gcm - 1;
            int ih = l_lcm, iv = 2;

            float d = 0.0f;
            if (l_gcm != 2 || l_lcm != 2) {
                int cap = 3 * N + 10;
                do {
                    int gcmix = GCMI(ix);
                    int lcmiv = LCMI(iv);
                    if (gcmix > lcmiv) {
                        int   gcmi1 = GCMI(ix + 1);
                        float xg  = GCMX(ix);
                        float xg1 = GCMX(ix + 1);
                        float xl  = LCMX(iv);
                        float t = ((float)(lcmiv - gcmi1) + 1.0f)
                                - (xl - xg1) * (float)(gcmix - gcmi1) / (xg - xg1);
                        iv++;
                        if (t >= d) { d = t; ig = ix + 1; ih = iv - 1; }
                    } else {
                        int   lcmiv1 = LCMI(iv - 1);
                        float xl1 = LCMX(iv - 1);
                        float xl  = LCMX(iv);
                        float xg  = GCMX(ix);
                        float t = (xg - xl1) * (float)(lcmiv - lcmiv1) / (xl - xl1)
                                - ((float)(gcmix - lcmiv1) - 1.0f);
                        ix--;
                        if (t > d) { d = t; ig = ix + 1; ih = iv; }
                    }
                    if (ix < 1) ix = 1;
                    if (iv > l_lcm) iv = l_lcm;
                } while (GCMI(ix) != LCMI(iv) && --cap > 0);
            } else {
                d = 1.0f;
            }

            if ((double)d < dip) {
                s_brk = 1;
            } else {
                s_brk = 0;
                s_ig = ig; s_ih = ih;
                ig0 = ig; ih0 = ih;
            }
        }
        __syncthreads();
        if (s_brk) break;

        float lm = 1.0f;
        if (tid < 512) {
            for (int j = s_ig; j < s_lgcm; j++) {
                int jb = GCMI(j + 1);
                int je = GCMI(j);
                if (je - jb > 1) {
                    float xb = GCMX(j + 1), xe = GCMX(j);
                    if (xe != xb) {
                        float C = (float)(je - jb) / (xe - xb);
                        for (int pos = jb + tid; pos <= je; pos += 512) {
                            float t = (float)(pos - jb + 1) - (XF(pos) - xb) * C;
                            lm = fmaxf(lm, t);
                        }
                    }
                }
            }
        } else {
            int t2 = tid - 512;
            for (int j = s_ih; j < s_llcm; j++) {
                int jb = LCMI(j);
                int je = LCMI(j + 1);
                if (je - jb > 1) {
                    float xb = LCMX(j), xe = LCMX(j + 1);
                    if (xe != xb) {
                        float C = (float)(je - jb) / (xe - xb);
                        for (int pos = jb + t2; pos <= je; pos += 512) {
                            float t = (XF(pos) - xb) * C - ((float)(pos - jb) - 1.0f);
                            lm = fmaxf(lm, t);
                        }
                    }
                }
            }
        }

        #pragma unroll
        for (int o = 16; o > 0; o >>= 1)
            lm = fmaxf(lm, __shfl_xor_sync(0xFFFFFFFFu, lm, o));
        if ((tid & 31) == 0) s_warp[tid >> 5] = lm;
        __syncthreads();
        if (tid < 32) {
            float v = s_warp[tid];
            #pragma unroll
            for (int o = 16; o > 0; o >>= 1)
                v = fmaxf(v, __shfl_xor_sync(0xFFFFFFFFu, v, o));
            if (tid == 0) s_max = v;
        }
        __syncthreads();

        if (tid == 0) {
            double dip_new = (double)s_max;
            if (dip < dip_new) dip = dip_new;
            int nlow = GCMI(ig0), nhigh = LCMI(ih0);
            if (low == nlow && high == nhigh) {
                s_brk = 1;
            } else {
                s_brk = 0;
                low = nlow; high = nhigh;
                s_low = low; s_high = high;
            }
        }
        __syncthreads();
        if (s_brk) break;
    }

    if (tid == 0) out[0] = (float)(dip / (2.0 * (double)N));

    #undef GCMI
    #undef GCMX
    #undef LCMI
    #undef LCMX
}

// ---------------------------------------------------------------------------
// Launch: 4 kernels.
// ---------------------------------------------------------------------------
extern "C" void kernel_launch(void* const* d_in, const int* in_sizes, int n_in,
                              void* d_out, int out_size)
{
    const float* X   = (const float*)d_in[0];
    const float* PV  = (const float*)d_in[1];
    const int*   idx = (const int*)d_in[2];
    float*       out = (float*)d_out;

    const int D = 128;
    const int N = in_sizes[0] / D;
    const int cs = (N + KCH - 1) / KCH;

    matvec_pad_kernel<<<(N * 16 + 255) / 256, 256>>>(X, PV, idx, N, D);
    sort_kernel<<<NBLK, 1024>>>();
    hull_kernel<<<NBLK, 1024>>>(N, cs);
    dip_kernel<<<1, 1024>>>(N, out);
}